// round 1
// baseline (speedup 1.0000x reference)
#include <cuda_runtime.h>

// Problem constants
#define N_    16
#define CIN   512
#define COUT  512
#define KK    3
#define HH    64
#define WW    64
#define SDIM  512
#define EPSF  1e-8f

// Conv tiling
#define CO_T  64      // couts per block
#define TH    16      // spatial tile height
#define TW    16      // spatial tile width
#define CCH   8       // cin chunk
#define XS    19      // padded smem row stride (conflict-free for this access pattern)

// Scratch (device globals; no allocation allowed)
__device__ float g_s[N_ * CIN];        // style modulation s[n, cin]
__device__ float g_wsq[COUT * CIN];    // sum over 3x3 taps of weight^2 (raw)
__device__ float g_demod[N_ * COUT];   // w_scale * rsqrt(w_scale^2 * sum + eps)

// ---------------------------------------------------------------------------
// s[n,c] = lin_scale * dot(style[n,:], style_w[c,:]) + style_b[c]
// grid = N_, block = 512
__global__ void k_style(const float* __restrict__ style,
                        const float* __restrict__ style_w,
                        const float* __restrict__ style_b) {
    __shared__ float sty[SDIM];
    int n = blockIdx.x;
    int c = threadIdx.x;
    sty[c] = style[n * SDIM + c];
    __syncthreads();
    const float lin_scale = rsqrtf((float)SDIM);
    const float* wr = style_w + c * SDIM;
    float acc = 0.f;
#pragma unroll 8
    for (int k = 0; k < SDIM; k++) acc += sty[k] * wr[k];
    g_s[n * CIN + c] = acc * lin_scale + style_b[c];
}

// ---------------------------------------------------------------------------
// wsq[o*CIN + i] = sum_t weight[(o*CIN+i)*9 + t]^2   (raw weights)
__global__ void k_wsq(const float* __restrict__ weight) {
    int idx = blockIdx.x * blockDim.x + threadIdx.x;
    if (idx >= COUT * CIN) return;
    const float* w = weight + idx * (KK * KK);
    float acc = 0.f;
#pragma unroll
    for (int t = 0; t < KK * KK; t++) acc += w[t] * w[t];
    g_wsq[idx] = acc;
}

// ---------------------------------------------------------------------------
// demod[n,o] = w_scale * rsqrt(w_scale^2 * sum_i wsq[o,i]*s[n,i]^2 + eps)
// grid = N_, block = 512
__global__ void k_demod() {
    __shared__ float s2[CIN];
    int n = blockIdx.x;
    int o = threadIdx.x;
    float sv = g_s[n * CIN + o];   // blockDim == CIN == COUT == 512
    s2[o] = sv * sv;
    __syncthreads();
    const float* wr = g_wsq + o * CIN;
    float acc = 0.f;
#pragma unroll 8
    for (int i = 0; i < CIN; i++) acc += wr[i] * s2[i];
    const float w_scale = rsqrtf((float)(CIN * KK * KK));
    g_demod[n * COUT + o] = w_scale * rsqrtf(w_scale * w_scale * acc + EPSF);
}

// ---------------------------------------------------------------------------
// Fused modulated conv: out[n,o,y,x] = demod[n,o] * sum_{i,kh,kw} W[o,i,kh,kw] * (x[n,i,y+kh-1,x+kw-1] * s[n,i])
// grid = (16 spatial tiles, 8 cout tiles, 16 n), block = 256
// Per thread: 8 couts x 8 pixels register tile.
__global__ void __launch_bounds__(256, 2)
k_conv(const float* __restrict__ x,
       const float* __restrict__ weight,
       float* __restrict__ out) {
    const int n      = blockIdx.z;
    const int cotile = blockIdx.y;
    const int sp     = blockIdx.x;
    const int ty0 = (sp >> 2) * TH;
    const int tx0 = (sp & 3) * TW;

    __shared__ float s_row[CIN];                 // s[n, :]
    __shared__ float xs[CCH][(TH + 2) * XS];     // modulated input tile + halo
    __shared__ float ws[CCH][KK * KK][CO_T];     // weights [ci][tap][co]

    const int t    = threadIdx.x;
    const int co_g = t >> 5;          // 0..7  (constant within a warp -> weight broadcast)
    const int px_g = t & 31;          // 0..31
    const int row  = px_g >> 1;       // 0..15
    const int col8 = (px_g & 1) * 8;  // 0 or 8

    // preload s[n,:]
#pragma unroll
    for (int i = t; i < CIN; i += 256) s_row[i] = g_s[n * CIN + i];

    float acc[8][8];
#pragma unroll
    for (int j = 0; j < 8; j++)
#pragma unroll
        for (int p = 0; p < 8; p++) acc[j][p] = 0.f;

    const float* xbase = x + (size_t)n * CIN * HH * WW;
    const float* wbase = weight + (size_t)(cotile * CO_T) * CIN * (KK * KK);

    for (int ci0 = 0; ci0 < CIN; ci0 += CCH) {
        __syncthreads();   // protect previous chunk's smem reads

        // ---- load modulated x tile with halo (zero pad at borders) ----
        for (int idx = t; idx < CCH * (TH + 2) * (TH + 2); idx += 256) {
            int ci = idx / ((TH + 2) * (TH + 2));
            int rem = idx - ci * ((TH + 2) * (TH + 2));
            int r = rem / (TH + 2);
            int c = rem - r * (TH + 2);
            int gy = ty0 + r - 1;
            int gx = tx0 + c - 1;
            float v = 0.f;
            if (gy >= 0 && gy < HH && gx >= 0 && gx < WW)
                v = xbase[((size_t)(ci0 + ci) * HH + gy) * WW + gx];
            xs[ci][r * XS + c] = v * s_row[ci0 + ci];
        }

        // ---- load weight chunk: [co][ci][tap] -> ws[ci][tap][co] ----
        for (int idx = t; idx < CO_T * CCH * (KK * KK); idx += 256) {
            int co  = idx / (CCH * KK * KK);
            int rem = idx - co * (CCH * KK * KK);
            int ci  = rem / (KK * KK);
            int tap = rem - ci * (KK * KK);
            ws[ci][tap][co] = wbase[((size_t)co * CIN + ci0 + ci) * (KK * KK) + tap];
        }
        __syncthreads();

        // ---- compute ----
#pragma unroll
        for (int ci = 0; ci < CCH; ci++) {
#pragma unroll
            for (int kh = 0; kh < 3; kh++) {
                float xr[10];
                const float* xp = &xs[ci][(row + kh) * XS + col8];
#pragma unroll
                for (int p = 0; p < 10; p++) xr[p] = xp[p];
#pragma unroll
                for (int kw = 0; kw < 3; kw++) {
                    const float4 w0 = *(const float4*)&ws[ci][kh * 3 + kw][co_g * 8];
                    const float4 w1 = *(const float4*)&ws[ci][kh * 3 + kw][co_g * 8 + 4];
                    float wv[8] = {w0.x, w0.y, w0.z, w0.w, w1.x, w1.y, w1.z, w1.w};
#pragma unroll
                    for (int j = 0; j < 8; j++)
#pragma unroll
                        for (int p = 0; p < 8; p++)
                            acc[j][p] += wv[j] * xr[p + kw];
                }
            }
        }
    }

    // ---- epilogue: apply w_scale*demod and store ----
#pragma unroll
    for (int j = 0; j < 8; j++) {
        int co = cotile * CO_T + co_g * 8 + j;
        float d = g_demod[n * COUT + co];
        float* orow = out + (((size_t)n * COUT + co) * HH + (ty0 + row)) * WW + tx0 + col8;
#pragma unroll
        for (int p = 0; p < 8; p++) orow[p] = acc[j][p] * d;
    }
}

// ---------------------------------------------------------------------------
extern "C" void kernel_launch(void* const* d_in, const int* in_sizes, int n_in,
                              void* d_out, int out_size) {
    const float* x       = (const float*)d_in[0];   // [16,512,64,64]
    const float* style   = (const float*)d_in[1];   // [16,512]
    const float* weight  = (const float*)d_in[2];   // [512,512,3,3]
    const float* style_w = (const float*)d_in[3];   // [512,512]
    const float* style_b = (const float*)d_in[4];   // [512]
    float* out = (float*)d_out;                     // [16,512,64,64]

    k_style<<<N_, SDIM>>>(style, style_w, style_b);
    k_wsq<<<(COUT * CIN + 255) / 256, 256>>>(weight);
    k_demod<<<N_, COUT>>>();

    dim3 grid(16, COUT / CO_T, N_);   // (spatial tiles, cout tiles, n)
    k_conv<<<grid, 256>>>(x, weight, out);
}

// round 2
// speedup vs baseline: 1.2687x; 1.2687x over previous
#include <cuda_runtime.h>

// Problem constants
#define N_    16
#define CIN   512
#define COUT  512
#define KK    3
#define HH    64
#define WW    64
#define SDIM  512
#define EPSF  1e-8f

// Conv tiling
#define CO_T  64      // couts per block
#define TH    16      // spatial tile height
#define TW    16      // spatial tile width
#define CCH   8       // cin chunk
#define XS    19      // padded smem row stride (conflict-free)

// Scratch (device globals; no allocation allowed)
__device__ float g_s[N_ * CIN];        // style modulation s[n, cin]
__device__ float g_wsq[COUT * CIN];    // sum over 3x3 taps of weight^2 (raw)
__device__ float g_demod[N_ * COUT];   // w_scale * rsqrt(w_scale^2 * sum + eps)

// ---------------------------------------------------------------------------
// packed f32x2 helpers (SASS FFMA2 path — only reachable via PTX)
__device__ __forceinline__ void ffma2(unsigned long long& d,
                                      unsigned long long a,
                                      unsigned long long b) {
    asm("fma.rn.f32x2 %0, %1, %2, %0;" : "+l"(d) : "l"(a), "l"(b));
}
__device__ __forceinline__ unsigned long long pk2(float lo, float hi) {
    unsigned long long r;
    asm("mov.b64 %0, {%1, %2};" : "=l"(r) : "f"(lo), "f"(hi));
    return r;
}
__device__ __forceinline__ void unpk2(float& lo, float& hi, unsigned long long v) {
    asm("mov.b64 {%0, %1}, %2;" : "=f"(lo), "=f"(hi) : "l"(v));
}

// ---------------------------------------------------------------------------
// s[n,c] = lin_scale * dot(style[n,:], style_w[c,:]) + style_b[c]
__global__ void k_style(const float* __restrict__ style,
                        const float* __restrict__ style_w,
                        const float* __restrict__ style_b) {
    __shared__ float sty[SDIM];
    int n = blockIdx.x;
    int c = threadIdx.x;
    sty[c] = style[n * SDIM + c];
    __syncthreads();
    const float lin_scale = rsqrtf((float)SDIM);
    const float* wr = style_w + c * SDIM;
    float acc = 0.f;
#pragma unroll 8
    for (int k = 0; k < SDIM; k++) acc += sty[k] * wr[k];
    g_s[n * CIN + c] = acc * lin_scale + style_b[c];
}

// ---------------------------------------------------------------------------
__global__ void k_wsq(const float* __restrict__ weight) {
    int idx = blockIdx.x * blockDim.x + threadIdx.x;
    if (idx >= COUT * CIN) return;
    const float* w = weight + idx * (KK * KK);
    float acc = 0.f;
#pragma unroll
    for (int t = 0; t < KK * KK; t++) acc += w[t] * w[t];
    g_wsq[idx] = acc;
}

// ---------------------------------------------------------------------------
__global__ void k_demod() {
    __shared__ float s2[CIN];
    int n = blockIdx.x;
    int o = threadIdx.x;
    float sv = g_s[n * CIN + o];
    s2[o] = sv * sv;
    __syncthreads();
    const float* wr = g_wsq + o * CIN;
    float acc = 0.f;
#pragma unroll 8
    for (int i = 0; i < CIN; i++) acc += wr[i] * s2[i];
    const float w_scale = rsqrtf((float)(CIN * KK * KK));
    g_demod[n * COUT + o] = w_scale * rsqrtf(w_scale * w_scale * acc + EPSF);
}

// ---------------------------------------------------------------------------
// Fused modulated conv, f32x2 packed along cout pairs.
// grid = (16 spatial tiles, 8 cout tiles, 16 n), block = 256
// Per thread: 4 cout-pairs x 8 pixels packed register tile (64 scalar accs).
__global__ void __launch_bounds__(256, 2)
k_conv(const float* __restrict__ x,
       const float* __restrict__ weight,
       float* __restrict__ out) {
    const int n      = blockIdx.z;
    const int cotile = blockIdx.y;
    const int sp     = blockIdx.x;
    const int ty0 = (sp >> 2) * TH;
    const int tx0 = (sp & 3) * TW;

    __shared__ float s_row[CIN];                 // s[n, :]
    __shared__ float xs[CCH][(TH + 2) * XS];     // modulated input tile + halo
    __shared__ float ws[CCH][KK * KK][CO_T];     // weights [ci][tap][co]

    const int t    = threadIdx.x;
    const int co_g = t >> 5;          // 0..7  (constant within a warp)
    const int px_g = t & 31;          // 0..31
    const int row  = px_g >> 1;       // 0..15
    const int col8 = (px_g & 1) * 8;  // 0 or 8

#pragma unroll
    for (int i = t; i < CIN; i += 256) s_row[i] = g_s[n * CIN + i];

    unsigned long long acc[4][8];     // [cout pair][pixel], packed f32x2
#pragma unroll
    for (int j = 0; j < 4; j++)
#pragma unroll
        for (int p = 0; p < 8; p++) acc[j][p] = 0ULL;

    const float* xbase = x + (size_t)n * CIN * HH * WW;
    const float* wbase = weight + (size_t)(cotile * CO_T) * CIN * (KK * KK);

    for (int ci0 = 0; ci0 < CIN; ci0 += CCH) {
        __syncthreads();

        // ---- load modulated x tile with halo (zero pad at borders) ----
        for (int idx = t; idx < CCH * (TH + 2) * (TH + 2); idx += 256) {
            int ci = idx / ((TH + 2) * (TH + 2));
            int rem = idx - ci * ((TH + 2) * (TH + 2));
            int r = rem / (TH + 2);
            int c = rem - r * (TH + 2);
            int gy = ty0 + r - 1;
            int gx = tx0 + c - 1;
            float v = 0.f;
            if (gy >= 0 && gy < HH && gx >= 0 && gx < WW)
                v = xbase[((size_t)(ci0 + ci) * HH + gy) * WW + gx];
            xs[ci][r * XS + c] = v * s_row[ci0 + ci];
        }

        // ---- load weight chunk: [co][ci][tap] -> ws[ci][tap][co] ----
        for (int idx = t; idx < CO_T * CCH * (KK * KK); idx += 256) {
            int co  = idx / (CCH * KK * KK);
            int rem = idx - co * (CCH * KK * KK);
            int ci  = rem / (KK * KK);
            int tap = rem - ci * (KK * KK);
            ws[ci][tap][co] = wbase[((size_t)co * CIN + ci0 + ci) * (KK * KK) + tap];
        }
        __syncthreads();

        // ---- compute ----
#pragma unroll
        for (int ci = 0; ci < CCH; ci++) {
#pragma unroll
            for (int kh = 0; kh < 3; kh++) {
                const float* xp = &xs[ci][(row + kh) * XS + col8];
                unsigned long long xrep[10];
#pragma unroll
                for (int p = 0; p < 10; p++) {
                    float v = xp[p];
                    xrep[p] = pk2(v, v);
                }
#pragma unroll
                for (int kw = 0; kw < 3; kw++) {
                    // adjacent-cout weight pairs straight from smem (8B aligned)
                    const unsigned long long* wp =
                        (const unsigned long long*)&ws[ci][kh * 3 + kw][co_g * 8];
                    unsigned long long w0 = wp[0];
                    unsigned long long w1 = wp[1];
                    unsigned long long w2 = wp[2];
                    unsigned long long w3 = wp[3];
#pragma unroll
                    for (int p = 0; p < 8; p++) {
                        ffma2(acc[0][p], w0, xrep[p + kw]);
                        ffma2(acc[1][p], w1, xrep[p + kw]);
                        ffma2(acc[2][p], w2, xrep[p + kw]);
                        ffma2(acc[3][p], w3, xrep[p + kw]);
                    }
                }
            }
        }
    }

    // ---- epilogue: apply w_scale*demod and store ----
#pragma unroll
    for (int j = 0; j < 4; j++) {
        int co0 = cotile * CO_T + co_g * 8 + 2 * j;
        float d0 = g_demod[n * COUT + co0];
        float d1 = g_demod[n * COUT + co0 + 1];
        float* orow0 = out + (((size_t)n * COUT + co0) * HH + (ty0 + row)) * WW + tx0 + col8;
        float* orow1 = orow0 + (size_t)HH * WW;
#pragma unroll
        for (int p = 0; p < 8; p++) {
            float lo, hi;
            unpk2(lo, hi, acc[j][p]);
            orow0[p] = lo * d0;
            orow1[p] = hi * d1;
        }
    }
}

// ---------------------------------------------------------------------------
extern "C" void kernel_launch(void* const* d_in, const int* in_sizes, int n_in,
                              void* d_out, int out_size) {
    const float* x       = (const float*)d_in[0];   // [16,512,64,64]
    const float* style   = (const float*)d_in[1];   // [16,512]
    const float* weight  = (const float*)d_in[2];   // [512,512,3,3]
    const float* style_w = (const float*)d_in[3];   // [512,512]
    const float* style_b = (const float*)d_in[4];   // [512]
    float* out = (float*)d_out;                     // [16,512,64,64]

    k_style<<<N_, SDIM>>>(style, style_w, style_b);
    k_wsq<<<(COUT * CIN + 255) / 256, 256>>>(weight);
    k_demod<<<N_, COUT>>>();

    dim3 grid(16, COUT / CO_T, N_);   // (spatial tiles, cout tiles, n)
    k_conv<<<grid, 256>>>(x, weight, out);
}

// round 5
// speedup vs baseline: 2.6452x; 2.0850x over previous
#include <cuda_runtime.h>
#include <cuda_bf16.h>
#include <cstdint>

// ---------------- problem constants ----------------
#define N_    16
#define CIN   512
#define COUT  512
#define HH    64
#define WW    64
#define SDIM  512
#define EPSF  1e-8f

// ---------------- GEMM tiling ----------------
#define TILE_M 128                 // pixels per CTA (2 rows x 64)
#define TILE_N 128                 // couts per CTA
#define KCH    32                  // ci per k-chunk
#define NITER  ((CIN / KCH) * 9)   // 144: tap outer, ci chunk inner
#define STAGES 3
#define ROWB   80                  // padded smem row stride (bytes) for 64B rows
#define ARR_B  (128 * ROWB)        // 10240 bytes per array (128 rows)
#define STAGE_B (4 * ARR_B)        // Ah, Al, Bh, Bl
#define SMEM_TOTAL (STAGES * STAGE_B + 512)

// ---------------- device scratch ----------------
__device__ float g_s[N_ * CIN];
__device__ float g_wsq[COUT * CIN];
__device__ float g_dm[N_ * COUT];
__device__ __nv_bfloat16 g_xh[(size_t)N_ * HH * WW * CIN];  // modulated x hi, NHWC
__device__ __nv_bfloat16 g_xl[(size_t)N_ * HH * WW * CIN];  // modulated x lo, NHWC
__device__ __nv_bfloat16 g_wh[(size_t)COUT * 9 * CIN];      // w*w_scale hi, [co][tap][ci]
__device__ __nv_bfloat16 g_wl[(size_t)COUT * 9 * CIN];      // w*w_scale lo

// ---------------- PTX helpers ----------------
__device__ __forceinline__ uint32_t smem_u32(const void* p) {
    uint32_t a;
    asm("{ .reg .u64 t; cvta.to.shared.u64 t, %1; cvt.u32.u64 %0, t; }" : "=r"(a) : "l"(p));
    return a;
}
__device__ __forceinline__ void cp16(uint32_t dst, const void* src, uint32_t srcsize) {
    asm volatile("cp.async.cg.shared.global [%0], [%1], 16, %2;"
                 :: "r"(dst), "l"(src), "r"(srcsize));
}
#define CP_COMMIT() asm volatile("cp.async.commit_group;" ::: "memory")
#define CP_WAIT2()  asm volatile("cp.async.wait_group 2;" ::: "memory")

__device__ __forceinline__ void ldm_x4(uint32_t r[4], uint32_t addr) {
    asm volatile("ldmatrix.sync.aligned.m8n8.x4.shared.b16 {%0,%1,%2,%3}, [%4];"
                 : "=r"(r[0]), "=r"(r[1]), "=r"(r[2]), "=r"(r[3]) : "r"(addr));
}
__device__ __forceinline__ void mma_bf16(float c[4], const uint32_t a[4],
                                         uint32_t b0, uint32_t b1) {
    asm volatile(
        "mma.sync.aligned.m16n8k16.row.col.f32.bf16.bf16.f32 "
        "{%0,%1,%2,%3}, {%4,%5,%6,%7}, {%8,%9}, {%0,%1,%2,%3};"
        : "+f"(c[0]), "+f"(c[1]), "+f"(c[2]), "+f"(c[3])
        : "r"(a[0]), "r"(a[1]), "r"(a[2]), "r"(a[3]), "r"(b0), "r"(b1));
}

// ---------------------------------------------------------------------------
__global__ void k_style(const float* __restrict__ style,
                        const float* __restrict__ style_w,
                        const float* __restrict__ style_b) {
    __shared__ float sty[SDIM];
    int n = blockIdx.x, c = threadIdx.x;
    sty[c] = style[n * SDIM + c];
    __syncthreads();
    const float lin_scale = rsqrtf((float)SDIM);
    const float* wr = style_w + c * SDIM;
    float acc = 0.f;
#pragma unroll 8
    for (int k = 0; k < SDIM; k++) acc += sty[k] * wr[k];
    g_s[n * CIN + c] = acc * lin_scale + style_b[c];
}

__global__ void k_wsq(const float* __restrict__ weight) {
    int idx = blockIdx.x * blockDim.x + threadIdx.x;
    if (idx >= COUT * CIN) return;
    const float* w = weight + (size_t)idx * 9;
    float acc = 0.f;
#pragma unroll
    for (int t = 0; t < 9; t++) acc += w[t] * w[t];
    g_wsq[idx] = acc;
}

__global__ void k_demod() {
    __shared__ float s2[CIN];
    int n = blockIdx.x, o = threadIdx.x;
    float sv = g_s[n * CIN + o];
    s2[o] = sv * sv;
    __syncthreads();
    const float* wr = g_wsq + o * CIN;
    float acc = 0.f;
#pragma unroll 8
    for (int i = 0; i < CIN; i++) acc += wr[i] * s2[i];
    const float ws = rsqrtf((float)(CIN * 9));
    g_dm[n * COUT + o] = rsqrtf(ws * ws * acc + EPSF);  // w_scale folded into weights
}

// modulated x -> NHWC bf16 hi/lo split
__global__ void k_xprep(const float* __restrict__ x) {
    __shared__ float tile[128][65];
    int y = blockIdx.x, n = blockIdx.y, t = threadIdx.x;
    for (int cic = 0; cic < 4; cic++) {
        __syncthreads();
        for (int idx = t; idx < 128 * 64; idx += 256) {
            int ci = idx >> 6, xx = idx & 63;
            int cg = cic * 128 + ci;
            float v = x[(((size_t)(n * CIN + cg)) * HH + y) * WW + xx];
            tile[ci][xx] = v * g_s[n * CIN + cg];
        }
        __syncthreads();
        for (int idx = t; idx < 128 * 64; idx += 256) {
            int ci = idx & 127, xx = idx >> 7;
            float v = tile[ci][xx];
            __nv_bfloat16 h = __float2bfloat16(v);
            __nv_bfloat16 l = __float2bfloat16(v - __bfloat162float(h));
            size_t o = ((size_t)((n * HH + y) * WW + xx)) * CIN + cic * 128 + ci;
            g_xh[o] = h;
            g_xl[o] = l;
        }
    }
}

// weights * w_scale -> [cout][tap][ci] bf16 hi/lo split
__global__ void k_wprep(const float* __restrict__ w) {
    int co = blockIdx.x, ci = threadIdx.x;
    const float ws = rsqrtf((float)(CIN * 9));
#pragma unroll
    for (int tap = 0; tap < 9; tap++) {
        float v = w[((size_t)co * CIN + ci) * 9 + tap] * ws;
        __nv_bfloat16 h = __float2bfloat16(v);
        __nv_bfloat16 l = __float2bfloat16(v - __bfloat162float(h));
        size_t o = ((size_t)co * 9 + tap) * CIN + ci;
        g_wh[o] = h;
        g_wl[o] = l;
    }
}

// ---------------------------------------------------------------------------
// Load one pipeline stage: A (128px x 32ci, hi+lo) + B (128co x 32ci, hi+lo).
__device__ __forceinline__ void load_stage(uint32_t sbase, int n, int y0, int co0,
                                           int j, int t) {
    const int tap = j >> 4;          // 0..8
    const int cic = j & 15;          // ci chunk 0..15
    const int dy = tap / 3 - 1, dx = tap % 3 - 1;
    // ---- A: 1024 16B chunks ----
#pragma unroll
    for (int u = 0; u < 4; u++) {
        int id = u * 256 + t;
        int split = id >> 9;
        int rem = id & 511;
        int row = rem >> 2;          // pixel 0..127
        int seg = rem & 3;
        int ys = y0 + (row >> 6) + dy;
        int xs = (row & 63) + dx;
        bool ok = (ys >= 0) & (ys < HH) & (xs >= 0) & (xs < WW);
        int ysc = ok ? ys : 0, xsc = ok ? xs : 0;
        const __nv_bfloat16* g = split ? g_xl : g_xh;
        const __nv_bfloat16* src =
            g + ((size_t)((n * HH + ysc) * WW + xsc)) * CIN + cic * KCH + seg * 8;
        uint32_t dst = sbase + split * ARR_B + row * ROWB + seg * 16;
        cp16(dst, src, ok ? 16u : 0u);
    }
    // ---- B: 1024 16B chunks ----
#pragma unroll
    for (int u = 0; u < 4; u++) {
        int id = u * 256 + t;
        int split = id >> 9;
        int rem = id & 511;
        int row = rem >> 2;          // cout 0..127
        int seg = rem & 3;
        const __nv_bfloat16* g = split ? g_wl : g_wh;
        const __nv_bfloat16* src =
            g + ((size_t)(co0 + row) * 9 + tap) * CIN + cic * KCH + seg * 8;
        uint32_t dst = sbase + 2 * ARR_B + split * ARR_B + row * ROWB + seg * 16;
        cp16(dst, src, 16u);
    }
}

// ---------------------------------------------------------------------------
// Implicit-GEMM modulated conv via bf16 mma.sync, 3-pass hi/lo split.
__global__ void __launch_bounds__(256, 1)
k_conv(float* __restrict__ out) {
    extern __shared__ __align__(16) char smem[];
    const uint32_t sb = smem_u32(smem);
    float* sdemod = (float*)(smem + STAGES * STAGE_B);

    const int t = threadIdx.x;
    const int lane = t & 31;
    const int w = t >> 5;
    const int warp_m = w & 3;          // 4 m-warps: 32 px each
    const int warp_n = w >> 2;         // 2 n-warps: 64 co each
    const int n = blockIdx.z;
    const int co0 = blockIdx.y * TILE_N;
    const int y0 = blockIdx.x * 2;

    if (t < TILE_N) sdemod[t] = g_dm[n * COUT + co0 + t];

    // per-thread ldmatrix base offsets (within a stage)
    const uint32_t a_off =
        (uint32_t)((warp_m * 32 + (lane & 15)) * ROWB + (lane >> 4) * 16);
    // B is [n][k] k-contiguous == col-major B for mma row.col:
    // matrix0 = (n0-7,k0-7)=b0, matrix1 = (n0-7,k8-15)=b1,
    // matrix2/3 = same for n8-15.  NON-trans ldmatrix.
    const uint32_t b_off =
        (uint32_t)(2 * ARR_B +
                   (warp_n * 64 + (lane & 7) + (lane >> 4) * 8) * ROWB +
                   ((lane >> 3) & 1) * 16);

    float acc[2][8][4];
#pragma unroll
    for (int mt = 0; mt < 2; mt++)
#pragma unroll
        for (int nt = 0; nt < 8; nt++)
#pragma unroll
            for (int q = 0; q < 4; q++) acc[mt][nt][q] = 0.f;

    // prologue: stages 0,1
    load_stage(sb + 0 * STAGE_B, n, y0, co0, 0, t);
    CP_COMMIT();
    load_stage(sb + 1 * STAGE_B, n, y0, co0, 1, t);
    CP_COMMIT();

    int st = 0;
    for (int j = 0; j < NITER; j++) {
        // prefetch stage j+2
        if (j + 2 < NITER) {
            int s2 = (j + 2) % STAGES;
            load_stage(sb + s2 * STAGE_B, n, y0, co0, j + 2, t);
        }
        CP_COMMIT();
        CP_WAIT2();
        __syncthreads();

        const uint32_t base = sb + st * STAGE_B;
#pragma unroll
        for (int ks = 0; ks < 2; ks++) {
            const uint32_t ko = ks * 32;
            uint32_t ah[2][4], al[2][4];
#pragma unroll
            for (int mt = 0; mt < 2; mt++) {
                ldm_x4(ah[mt], base + a_off + mt * 16 * ROWB + ko);
                ldm_x4(al[mt], base + ARR_B + a_off + mt * 16 * ROWB + ko);
            }
            uint32_t bh[4][4], bl[4][4];
#pragma unroll
            for (int p = 0; p < 4; p++) {
                ldm_x4(bh[p], base + b_off + p * 16 * ROWB + ko);
                ldm_x4(bl[p], base + ARR_B + b_off + p * 16 * ROWB + ko);
            }
#pragma unroll
            for (int mt = 0; mt < 2; mt++) {
#pragma unroll
                for (int nt = 0; nt < 8; nt++) {
                    const int p = nt >> 1, h = (nt & 1) * 2;
                    mma_bf16(acc[mt][nt], ah[mt], bh[p][h], bh[p][h + 1]);
                    mma_bf16(acc[mt][nt], ah[mt], bl[p][h], bl[p][h + 1]);
                    mma_bf16(acc[mt][nt], al[mt], bh[p][h], bh[p][h + 1]);
                }
            }
        }
        __syncthreads();
        st = (st + 1) % STAGES;
    }

    // ---- epilogue: demod + scatter to NCHW ----
    const int r0 = lane >> 2;
    const int c0 = (lane & 3) * 2;
#pragma unroll
    for (int mt = 0; mt < 2; mt++) {
#pragma unroll
        for (int nt = 0; nt < 8; nt++) {
            int col = warp_n * 64 + nt * 8 + c0;        // co - co0
            float d0 = sdemod[col], d1 = sdemod[col + 1];
#pragma unroll
            for (int half = 0; half < 2; half++) {
                int p = warp_m * 32 + mt * 16 + r0 + half * 8;   // pixel 0..127
                int y = y0 + (p >> 6);
                int xo = p & 63;
                size_t o = (((size_t)(n * COUT + co0 + col)) * HH + y) * WW + xo;
                out[o] = acc[mt][nt][half * 2] * d0;
                out[o + (size_t)HH * WW] = acc[mt][nt][half * 2 + 1] * d1;
            }
        }
    }
}

// ---------------------------------------------------------------------------
extern "C" void kernel_launch(void* const* d_in, const int* in_sizes, int n_in,
                              void* d_out, int out_size) {
    const float* x       = (const float*)d_in[0];   // [16,512,64,64]
    const float* style   = (const float*)d_in[1];   // [16,512]
    const float* weight  = (const float*)d_in[2];   // [512,512,3,3]
    const float* style_w = (const float*)d_in[3];   // [512,512]
    const float* style_b = (const float*)d_in[4];   // [512]
    float* out = (float*)d_out;                     // [16,512,64,64]

    k_style<<<N_, SDIM>>>(style, style_w, style_b);
    k_wsq<<<(COUT * CIN + 255) / 256, 256>>>(weight);
    k_demod<<<N_, COUT>>>();
    dim3 xg(HH, N_);
    k_xprep<<<xg, 256>>>(x);
    k_wprep<<<COUT, CIN>>>(weight);

    cudaFuncSetAttribute(k_conv, cudaFuncAttributeMaxDynamicSharedMemorySize, SMEM_TOTAL);
    dim3 grid(HH / 2, COUT / TILE_N, N_);            // (32 row-pairs, 4 co tiles, 16 n)
    k_conv<<<grid, 256, SMEM_TOTAL>>>(out);
}

// round 6
// speedup vs baseline: 3.5489x; 1.3416x over previous
#include <cuda_runtime.h>
#include <cuda_fp16.h>
#include <cstdint>

// ---------------- problem constants ----------------
#define N_    16
#define CIN   512
#define COUT  512
#define HH    64
#define WW    64
#define SDIM  512
#define EPSF  1e-8f

// ---------------- GEMM tiling ----------------
#define TILE_M 128                 // pixels per CTA (2 rows x 64)
#define TILE_N 128                 // couts per CTA
#define KCH    32                  // ci per k-chunk
#define NITER  ((CIN / KCH) * 9)   // 144: tap outer, ci chunk inner
#define STAGES 3
#define ROWB   80                  // padded smem row stride (bytes) for 64B rows
#define ARR_B  (128 * ROWB)        // 10240 bytes per array (128 rows)
#define STAGE_B (3 * ARR_B)        // Ah, Al, Bh
#define SMEM_TOTAL (STAGES * STAGE_B + 512)

// ---------------- device scratch ----------------
__device__ float g_s[N_ * CIN];
__device__ float g_wsq[COUT * CIN];
__device__ float g_dm[N_ * COUT];
__device__ __half g_xh[(size_t)N_ * HH * WW * CIN];  // modulated x hi, NHWC
__device__ __half g_xl[(size_t)N_ * HH * WW * CIN];  // modulated x lo, NHWC
__device__ __half g_wh[(size_t)COUT * 9 * CIN];      // w*w_scale fp16, [co][tap][ci]

// ---------------- PTX helpers ----------------
__device__ __forceinline__ uint32_t smem_u32(const void* p) {
    uint32_t a;
    asm("{ .reg .u64 t; cvta.to.shared.u64 t, %1; cvt.u32.u64 %0, t; }" : "=r"(a) : "l"(p));
    return a;
}
__device__ __forceinline__ void cp16(uint32_t dst, const void* src, uint32_t srcsize) {
    asm volatile("cp.async.cg.shared.global [%0], [%1], 16, %2;"
                 :: "r"(dst), "l"(src), "r"(srcsize));
}
#define CP_COMMIT() asm volatile("cp.async.commit_group;" ::: "memory")
#define CP_WAIT2()  asm volatile("cp.async.wait_group 2;" ::: "memory")

__device__ __forceinline__ void ldm_x4(uint32_t r[4], uint32_t addr) {
    asm volatile("ldmatrix.sync.aligned.m8n8.x4.shared.b16 {%0,%1,%2,%3}, [%4];"
                 : "=r"(r[0]), "=r"(r[1]), "=r"(r[2]), "=r"(r[3]) : "r"(addr));
}
__device__ __forceinline__ void mma_f16(float c[4], const uint32_t a[4],
                                        uint32_t b0, uint32_t b1) {
    asm volatile(
        "mma.sync.aligned.m16n8k16.row.col.f32.f16.f16.f32 "
        "{%0,%1,%2,%3}, {%4,%5,%6,%7}, {%8,%9}, {%0,%1,%2,%3};"
        : "+f"(c[0]), "+f"(c[1]), "+f"(c[2]), "+f"(c[3])
        : "r"(a[0]), "r"(a[1]), "r"(a[2]), "r"(a[3]), "r"(b0), "r"(b1));
}

// ---------------------------------------------------------------------------
__global__ void k_style(const float* __restrict__ style,
                        const float* __restrict__ style_w,
                        const float* __restrict__ style_b) {
    __shared__ float sty[SDIM];
    int n = blockIdx.x, c = threadIdx.x;
    sty[c] = style[n * SDIM + c];
    __syncthreads();
    const float lin_scale = rsqrtf((float)SDIM);
    const float* wr = style_w + c * SDIM;
    float acc = 0.f;
#pragma unroll 8
    for (int k = 0; k < SDIM; k++) acc += sty[k] * wr[k];
    g_s[n * CIN + c] = acc * lin_scale + style_b[c];
}

__global__ void k_wsq(const float* __restrict__ weight) {
    int idx = blockIdx.x * blockDim.x + threadIdx.x;
    if (idx >= COUT * CIN) return;
    const float* w = weight + (size_t)idx * 9;
    float acc = 0.f;
#pragma unroll
    for (int t = 0; t < 9; t++) acc += w[t] * w[t];
    g_wsq[idx] = acc;
}

__global__ void k_demod() {
    __shared__ float s2[CIN];
    int n = blockIdx.x, o = threadIdx.x;
    float sv = g_s[n * CIN + o];
    s2[o] = sv * sv;
    __syncthreads();
    const float* wr = g_wsq + o * CIN;
    float acc = 0.f;
#pragma unroll 8
    for (int i = 0; i < CIN; i++) acc += wr[i] * s2[i];
    const float ws = rsqrtf((float)(CIN * 9));
    g_dm[n * COUT + o] = rsqrtf(ws * ws * acc + EPSF);  // w_scale folded into weights
}

// modulated x -> NHWC fp16 hi/lo split
__global__ void k_xprep(const float* __restrict__ x) {
    __shared__ float tile[128][65];
    int y = blockIdx.x, n = blockIdx.y, t = threadIdx.x;
    for (int cic = 0; cic < 4; cic++) {
        __syncthreads();
        for (int idx = t; idx < 128 * 64; idx += 256) {
            int ci = idx >> 6, xx = idx & 63;
            int cg = cic * 128 + ci;
            float v = x[(((size_t)(n * CIN + cg)) * HH + y) * WW + xx];
            tile[ci][xx] = v * g_s[n * CIN + cg];
        }
        __syncthreads();
        for (int idx = t; idx < 128 * 64; idx += 256) {
            int ci = idx & 127, xx = idx >> 7;
            float v = tile[ci][xx];
            __half h = __float2half(v);
            __half l = __float2half(v - __half2float(h));
            size_t o = ((size_t)((n * HH + y) * WW + xx)) * CIN + cic * 128 + ci;
            g_xh[o] = h;
            g_xl[o] = l;
        }
    }
}

// weights * w_scale -> [cout][tap][ci] fp16
__global__ void k_wprep(const float* __restrict__ w) {
    int co = blockIdx.x, ci = threadIdx.x;
    const float ws = rsqrtf((float)(CIN * 9));
#pragma unroll
    for (int tap = 0; tap < 9; tap++) {
        float v = w[((size_t)co * CIN + ci) * 9 + tap] * ws;
        g_wh[((size_t)co * 9 + tap) * CIN + ci] = __float2half(v);
    }
}

// ---------------------------------------------------------------------------
// Load one pipeline stage: A (128px x 32ci, hi+lo) + B (128co x 32ci).
__device__ __forceinline__ void load_stage(uint32_t sbase, int n, int y0, int co0,
                                           int j, int t) {
    const int tap = j >> 4;          // 0..8
    const int cic = j & 15;          // ci chunk 0..15
    const int dy = tap / 3 - 1, dx = tap % 3 - 1;
    // ---- A: 1024 16B chunks (hi then lo) ----
#pragma unroll
    for (int u = 0; u < 4; u++) {
        int id = u * 256 + t;
        int split = id >> 9;
        int rem = id & 511;
        int row = rem >> 2;          // pixel 0..127
        int seg = rem & 3;
        int ys = y0 + (row >> 6) + dy;
        int xs = (row & 63) + dx;
        bool ok = (ys >= 0) & (ys < HH) & (xs >= 0) & (xs < WW);
        int ysc = ok ? ys : 0, xsc = ok ? xs : 0;
        const __half* g = split ? g_xl : g_xh;
        const __half* src =
            g + ((size_t)((n * HH + ysc) * WW + xsc)) * CIN + cic * KCH + seg * 8;
        uint32_t dst = sbase + split * ARR_B + row * ROWB + seg * 16;
        cp16(dst, src, ok ? 16u : 0u);
    }
    // ---- B: 512 16B chunks ----
#pragma unroll
    for (int u = 0; u < 2; u++) {
        int id = u * 256 + t;
        int row = id >> 2;           // cout 0..127
        int seg = id & 3;
        const __half* src =
            g_wh + ((size_t)(co0 + row) * 9 + tap) * CIN + cic * KCH + seg * 8;
        uint32_t dst = sbase + 2 * ARR_B + row * ROWB + seg * 16;
        cp16(dst, src, 16u);
    }
}

// ---------------------------------------------------------------------------
// Implicit-GEMM modulated conv via fp16 mma.sync, 2-pass x hi/lo split.
__global__ void __launch_bounds__(256, 1)
k_conv(float* __restrict__ out) {
    extern __shared__ __align__(16) char smem[];
    const uint32_t sb = smem_u32(smem);
    float* sdemod = (float*)(smem + STAGES * STAGE_B);

    const int t = threadIdx.x;
    const int lane = t & 31;
    const int w = t >> 5;
    const int warp_m = w & 3;          // 4 m-warps: 32 px each
    const int warp_n = w >> 2;         // 2 n-warps: 64 co each
    const int n = blockIdx.z;
    const int co0 = blockIdx.y * TILE_N;
    const int y0 = blockIdx.x * 2;

    if (t < TILE_N) sdemod[t] = g_dm[n * COUT + co0 + t];

    const uint32_t a_off =
        (uint32_t)((warp_m * 32 + (lane & 15)) * ROWB + (lane >> 4) * 16);
    // B is [n][k] k-contiguous == col-major B for mma row.col; NON-trans ldmatrix.
    const uint32_t b_off =
        (uint32_t)(2 * ARR_B +
                   (warp_n * 64 + (lane & 7) + (lane >> 4) * 8) * ROWB +
                   ((lane >> 3) & 1) * 16);

    float acc[2][8][4];
#pragma unroll
    for (int mt = 0; mt < 2; mt++)
#pragma unroll
        for (int nt = 0; nt < 8; nt++)
#pragma unroll
            for (int q = 0; q < 4; q++) acc[mt][nt][q] = 0.f;

    // prologue: stages 0,1
    load_stage(sb + 0 * STAGE_B, n, y0, co0, 0, t);
    CP_COMMIT();
    load_stage(sb + 1 * STAGE_B, n, y0, co0, 1, t);
    CP_COMMIT();

    int st = 0;
    for (int j = 0; j < NITER; j++) {
        if (j + 2 < NITER) {
            int s2 = (j + 2) % STAGES;
            load_stage(sb + s2 * STAGE_B, n, y0, co0, j + 2, t);
        }
        CP_COMMIT();
        CP_WAIT2();
        __syncthreads();

        const uint32_t base = sb + st * STAGE_B;
#pragma unroll
        for (int ks = 0; ks < 2; ks++) {
            const uint32_t ko = ks * 32;
            uint32_t ah[2][4], al[2][4];
#pragma unroll
            for (int mt = 0; mt < 2; mt++) {
                ldm_x4(ah[mt], base + a_off + mt * 16 * ROWB + ko);
                ldm_x4(al[mt], base + ARR_B + a_off + mt * 16 * ROWB + ko);
            }
            uint32_t bh[4][4];
#pragma unroll
            for (int p = 0; p < 4; p++)
                ldm_x4(bh[p], base + b_off + p * 16 * ROWB + ko);
#pragma unroll
            for (int mt = 0; mt < 2; mt++) {
#pragma unroll
                for (int nt = 0; nt < 8; nt++) {
                    const int p = nt >> 1, h = (nt & 1) * 2;
                    mma_f16(acc[mt][nt], ah[mt], bh[p][h], bh[p][h + 1]);
                    mma_f16(acc[mt][nt], al[mt], bh[p][h], bh[p][h + 1]);
                }
            }
        }
        __syncthreads();
        st = (st + 1) % STAGES;
    }

    // ---- epilogue: demod + scatter to NCHW ----
    const int r0 = lane >> 2;
    const int c0 = (lane & 3) * 2;
#pragma unroll
    for (int mt = 0; mt < 2; mt++) {
#pragma unroll
        for (int nt = 0; nt < 8; nt++) {
            int col = warp_n * 64 + nt * 8 + c0;        // co - co0
            float d0 = sdemod[col], d1 = sdemod[col + 1];
#pragma unroll
            for (int half = 0; half < 2; half++) {
                int p = warp_m * 32 + mt * 16 + r0 + half * 8;   // pixel 0..127
                int y = y0 + (p >> 6);
                int xo = p & 63;
                size_t o = (((size_t)(n * COUT + co0 + col)) * HH + y) * WW + xo;
                out[o] = acc[mt][nt][half * 2] * d0;
                out[o + (size_t)HH * WW] = acc[mt][nt][half * 2 + 1] * d1;
            }
        }
    }
}

// ---------------------------------------------------------------------------
extern "C" void kernel_launch(void* const* d_in, const int* in_sizes, int n_in,
                              void* d_out, int out_size) {
    const float* x       = (const float*)d_in[0];   // [16,512,64,64]
    const float* style   = (const float*)d_in[1];   // [16,512]
    const float* weight  = (const float*)d_in[2];   // [512,512,3,3]
    const float* style_w = (const float*)d_in[3];   // [512,512]
    const float* style_b = (const float*)d_in[4];   // [512]
    float* out = (float*)d_out;                     // [16,512,64,64]

    k_style<<<N_, SDIM>>>(style, style_w, style_b);
    k_wsq<<<(COUT * CIN + 255) / 256, 256>>>(weight);
    k_demod<<<N_, COUT>>>();
    dim3 xg(HH, N_);
    k_xprep<<<xg, 256>>>(x);
    k_wprep<<<COUT, CIN>>>(weight);

    cudaFuncSetAttribute(k_conv, cudaFuncAttributeMaxDynamicSharedMemorySize, SMEM_TOTAL);
    dim3 grid(HH / 2, COUT / TILE_N, N_);            // (32 row-pairs, 4 co tiles, 16 n)
    k_conv<<<grid, 256, SMEM_TOTAL>>>(out);
}

// round 7
// speedup vs baseline: 6.4108x; 1.8064x over previous
#include <cuda_runtime.h>
#include <cuda_fp16.h>
#include <cstdint>

// ---------------- problem constants ----------------
#define N_    16
#define CIN   512
#define COUT  512
#define HH    64
#define WW    64
#define SDIM  512
#define EPSF  1e-8f

// ---------------- GEMM tiling ----------------
#define TILE_M 128                 // pixels per CTA (2 rows x 64)
#define TILE_N 128                 // couts per CTA
#define KCH    32                  // ci per k-chunk
#define NITER  ((CIN / KCH) * 9)   // 144: tap outer, ci chunk inner
#define STAGES 3
#define ROWB   80                  // padded smem row stride (bytes) for 64B rows
#define ARR_B  (128 * ROWB)        // 10240 bytes per array (128 rows)
#define STAGE_B (2 * ARR_B)        // A, B
#define SMEM_TOTAL (STAGES * STAGE_B + 512)

// ---------------- device scratch ----------------
__device__ float g_s[N_ * CIN];
__device__ float g_wsq[COUT * CIN];
__device__ float g_dm[N_ * COUT];
__device__ __half g_xh[(size_t)N_ * HH * WW * CIN];  // modulated x fp16, NHWC
__device__ __half g_wh[(size_t)COUT * 9 * CIN];      // w*w_scale fp16, [co][tap][ci]

// ---------------- PTX helpers ----------------
__device__ __forceinline__ uint32_t smem_u32(const void* p) {
    uint32_t a;
    asm("{ .reg .u64 t; cvta.to.shared.u64 t, %1; cvt.u32.u64 %0, t; }" : "=r"(a) : "l"(p));
    return a;
}
__device__ __forceinline__ void cp16(uint32_t dst, const void* src, uint32_t srcsize) {
    asm volatile("cp.async.cg.shared.global [%0], [%1], 16, %2;"
                 :: "r"(dst), "l"(src), "r"(srcsize));
}
#define CP_COMMIT() asm volatile("cp.async.commit_group;" ::: "memory")
#define CP_WAIT2()  asm volatile("cp.async.wait_group 2;" ::: "memory")

__device__ __forceinline__ void ldm_x4(uint32_t r[4], uint32_t addr) {
    asm volatile("ldmatrix.sync.aligned.m8n8.x4.shared.b16 {%0,%1,%2,%3}, [%4];"
                 : "=r"(r[0]), "=r"(r[1]), "=r"(r[2]), "=r"(r[3]) : "r"(addr));
}
__device__ __forceinline__ void mma_f16(float c[4], const uint32_t a[4],
                                        uint32_t b0, uint32_t b1) {
    asm volatile(
        "mma.sync.aligned.m16n8k16.row.col.f32.f16.f16.f32 "
        "{%0,%1,%2,%3}, {%4,%5,%6,%7}, {%8,%9}, {%0,%1,%2,%3};"
        : "+f"(c[0]), "+f"(c[1]), "+f"(c[2]), "+f"(c[3])
        : "r"(a[0]), "r"(a[1]), "r"(a[2]), "r"(a[3]), "r"(b0), "r"(b1));
}

// ---------------------------------------------------------------------------
__global__ void k_style(const float* __restrict__ style,
                        const float* __restrict__ style_w,
                        const float* __restrict__ style_b) {
    __shared__ float sty[SDIM];
    int n = blockIdx.x, c = threadIdx.x;
    sty[c] = style[n * SDIM + c];
    __syncthreads();
    const float lin_scale = rsqrtf((float)SDIM);
    const float* wr = style_w + c * SDIM;
    float acc = 0.f;
#pragma unroll 8
    for (int k = 0; k < SDIM; k++) acc += sty[k] * wr[k];
    g_s[n * CIN + c] = acc * lin_scale + style_b[c];
}

__global__ void k_wsq(const float* __restrict__ weight) {
    int idx = blockIdx.x * blockDim.x + threadIdx.x;
    if (idx >= COUT * CIN) return;
    const float* w = weight + (size_t)idx * 9;
    float acc = 0.f;
#pragma unroll
    for (int t = 0; t < 9; t++) acc += w[t] * w[t];
    g_wsq[idx] = acc;
}

__global__ void k_demod() {
    __shared__ float s2[CIN];
    int n = blockIdx.x, o = threadIdx.x;
    float sv = g_s[n * CIN + o];
    s2[o] = sv * sv;
    __syncthreads();
    const float* wr = g_wsq + o * CIN;
    float acc = 0.f;
#pragma unroll 8
    for (int i = 0; i < CIN; i++) acc += wr[i] * s2[i];
    const float ws = rsqrtf((float)(CIN * 9));
    g_dm[n * COUT + o] = rsqrtf(ws * ws * acc + EPSF);  // w_scale folded into weights
}

// modulated x -> NHWC fp16
__global__ void k_xprep(const float* __restrict__ x) {
    __shared__ float tile[128][65];
    int y = blockIdx.x, n = blockIdx.y, t = threadIdx.x;
    for (int cic = 0; cic < 4; cic++) {
        __syncthreads();
        for (int idx = t; idx < 128 * 64; idx += 256) {
            int ci = idx >> 6, xx = idx & 63;
            int cg = cic * 128 + ci;
            float v = x[(((size_t)(n * CIN + cg)) * HH + y) * WW + xx];
            tile[ci][xx] = v * g_s[n * CIN + cg];
        }
        __syncthreads();
        for (int idx = t; idx < 128 * 64; idx += 256) {
            int ci = idx & 127, xx = idx >> 7;
            size_t o = ((size_t)((n * HH + y) * WW + xx)) * CIN + cic * 128 + ci;
            g_xh[o] = __float2half(tile[ci][xx]);
        }
    }
}

// weights * w_scale -> [cout][tap][ci] fp16
__global__ void k_wprep(const float* __restrict__ w) {
    int co = blockIdx.x, ci = threadIdx.x;
    const float ws = rsqrtf((float)(CIN * 9));
#pragma unroll
    for (int tap = 0; tap < 9; tap++) {
        float v = w[((size_t)co * CIN + ci) * 9 + tap] * ws;
        g_wh[((size_t)co * 9 + tap) * CIN + ci] = __float2half(v);
    }
}

// ---------------------------------------------------------------------------
// Load one pipeline stage: A (128px x 32ci) + B (128co x 32ci).
__device__ __forceinline__ void load_stage(uint32_t sbase, int n, int y0, int co0,
                                           int j, int t) {
    const int tap = j >> 4;          // 0..8
    const int cic = j & 15;          // ci chunk 0..15
    const int dy = tap / 3 - 1, dx = tap % 3 - 1;
    // ---- A: 512 16B chunks ----
#pragma unroll
    for (int u = 0; u < 2; u++) {
        int id = u * 256 + t;
        int row = id >> 2;           // pixel 0..127
        int seg = id & 3;
        int ys = y0 + (row >> 6) + dy;
        int xs = (row & 63) + dx;
        bool ok = (ys >= 0) & (ys < HH) & (xs >= 0) & (xs < WW);
        int ysc = ok ? ys : 0, xsc = ok ? xs : 0;
        const __half* src =
            g_xh + ((size_t)((n * HH + ysc) * WW + xsc)) * CIN + cic * KCH + seg * 8;
        uint32_t dst = sbase + row * ROWB + seg * 16;
        cp16(dst, src, ok ? 16u : 0u);
    }
    // ---- B: 512 16B chunks ----
#pragma unroll
    for (int u = 0; u < 2; u++) {
        int id = u * 256 + t;
        int row = id >> 2;           // cout 0..127
        int seg = id & 3;
        const __half* src =
            g_wh + ((size_t)(co0 + row) * 9 + tap) * CIN + cic * KCH + seg * 8;
        uint32_t dst = sbase + ARR_B + row * ROWB + seg * 16;
        cp16(dst, src, 16u);
    }
}

// ---------------------------------------------------------------------------
// Implicit-GEMM modulated conv via fp16 mma.sync, single pass.
__global__ void __launch_bounds__(256, 2)
k_conv(float* __restrict__ out) {
    extern __shared__ __align__(16) char smem[];
    const uint32_t sb = smem_u32(smem);
    float* sdemod = (float*)(smem + STAGES * STAGE_B);

    const int t = threadIdx.x;
    const int lane = t & 31;
    const int w = t >> 5;
    const int warp_m = w & 3;          // 4 m-warps: 32 px each
    const int warp_n = w >> 2;         // 2 n-warps: 64 co each
    const int n = blockIdx.z;
    const int co0 = blockIdx.y * TILE_N;
    const int y0 = blockIdx.x * 2;

    if (t < TILE_N) sdemod[t] = g_dm[n * COUT + co0 + t];

    const uint32_t a_off =
        (uint32_t)((warp_m * 32 + (lane & 15)) * ROWB + (lane >> 4) * 16);
    // B is [n][k] k-contiguous == col-major B for mma row.col; NON-trans ldmatrix.
    const uint32_t b_off =
        (uint32_t)(ARR_B +
                   (warp_n * 64 + (lane & 7) + (lane >> 4) * 8) * ROWB +
                   ((lane >> 3) & 1) * 16);

    float acc[2][8][4];
#pragma unroll
    for (int mt = 0; mt < 2; mt++)
#pragma unroll
        for (int nt = 0; nt < 8; nt++)
#pragma unroll
            for (int q = 0; q < 4; q++) acc[mt][nt][q] = 0.f;

    // prologue: stages 0,1
    load_stage(sb + 0 * STAGE_B, n, y0, co0, 0, t);
    CP_COMMIT();
    load_stage(sb + 1 * STAGE_B, n, y0, co0, 1, t);
    CP_COMMIT();

    int st = 0;
    for (int j = 0; j < NITER; j++) {
        if (j + 2 < NITER) {
            int s2 = (j + 2) % STAGES;
            load_stage(sb + s2 * STAGE_B, n, y0, co0, j + 2, t);
        }
        CP_COMMIT();
        CP_WAIT2();
        __syncthreads();

        const uint32_t base = sb + st * STAGE_B;
#pragma unroll
        for (int ks = 0; ks < 2; ks++) {
            const uint32_t ko = ks * 32;
            uint32_t ah[2][4];
#pragma unroll
            for (int mt = 0; mt < 2; mt++)
                ldm_x4(ah[mt], base + a_off + mt * 16 * ROWB + ko);
            uint32_t bh[4][4];
#pragma unroll
            for (int p = 0; p < 4; p++)
                ldm_x4(bh[p], base + b_off + p * 16 * ROWB + ko);
#pragma unroll
            for (int mt = 0; mt < 2; mt++) {
#pragma unroll
                for (int nt = 0; nt < 8; nt++) {
                    const int p = nt >> 1, h = (nt & 1) * 2;
                    mma_f16(acc[mt][nt], ah[mt], bh[p][h], bh[p][h + 1]);
                }
            }
        }
        __syncthreads();
        st = (st + 1) % STAGES;
    }

    // ---- epilogue: demod + scatter to NCHW ----
    const int r0 = lane >> 2;
    const int c0 = (lane & 3) * 2;
#pragma unroll
    for (int mt = 0; mt < 2; mt++) {
#pragma unroll
        for (int nt = 0; nt < 8; nt++) {
            int col = warp_n * 64 + nt * 8 + c0;        // co - co0
            float d0 = sdemod[col], d1 = sdemod[col + 1];
#pragma unroll
            for (int half = 0; half < 2; half++) {
                int p = warp_m * 32 + mt * 16 + r0 + half * 8;   // pixel 0..127
                int y = y0 + (p >> 6);
                int xo = p & 63;
                size_t o = (((size_t)(n * COUT + co0 + col)) * HH + y) * WW + xo;
                out[o] = acc[mt][nt][half * 2] * d0;
                out[o + (size_t)HH * WW] = acc[mt][nt][half * 2 + 1] * d1;
            }
        }
    }
}

// ---------------------------------------------------------------------------
extern "C" void kernel_launch(void* const* d_in, const int* in_sizes, int n_in,
                              void* d_out, int out_size) {
    const float* x       = (const float*)d_in[0];   // [16,512,64,64]
    const float* style   = (const float*)d_in[1];   // [16,512]
    const float* weight  = (const float*)d_in[2];   // [512,512,3,3]
    const float* style_w = (const float*)d_in[3];   // [512,512]
    const float* style_b = (const float*)d_in[4];   // [512]
    float* out = (float*)d_out;                     // [16,512,64,64]

    k_style<<<N_, SDIM>>>(style, style_w, style_b);
    k_wsq<<<(COUT * CIN + 255) / 256, 256>>>(weight);
    k_demod<<<N_, COUT>>>();
    dim3 xg(HH, N_);
    k_xprep<<<xg, 256>>>(x);
    k_wprep<<<COUT, CIN>>>(weight);

    cudaFuncSetAttribute(k_conv, cudaFuncAttributeMaxDynamicSharedMemorySize, SMEM_TOTAL);
    dim3 grid(HH / 2, COUT / TILE_N, N_);            // (32 row-pairs, 4 co tiles, 16 n)
    k_conv<<<grid, 256, SMEM_TOTAL>>>(out);
}

// round 8
// speedup vs baseline: 8.2600x; 1.2885x over previous
#include <cuda_runtime.h>
#include <cuda_fp16.h>
#include <cstdint>

// ---------------- problem constants ----------------
#define N_    16
#define CIN   512
#define COUT  512
#define HH    64
#define WW    64
#define SDIM  512
#define EPSF  1e-8f

// ---------------- GEMM tiling ----------------
#define TILE_M 128                 // pixels per CTA (2 rows x 64)
#define TILE_N 128                 // couts per CTA
#define KCH    32                  // ci per k-chunk
#define NITER  ((CIN / KCH) * 9)   // 144: tap outer, ci chunk inner
#define STAGES 3
#define ROWB   80                  // padded smem row stride (bytes) for 64B rows
#define ARR_B  (128 * ROWB)        // 10240 bytes per array (128 rows)
#define STAGE_B (2 * ARR_B)        // A, B
#define SMEM_TOTAL (STAGES * STAGE_B + 512)

// ---------------- device scratch ----------------
__device__ float g_s[N_ * CIN];
__device__ float g_wsq[COUT * CIN];
__device__ float g_dm[N_ * COUT];
__device__ __half g_xh[(size_t)N_ * HH * WW * CIN];  // modulated x fp16, NHWC
__device__ __half g_wh[(size_t)COUT * 9 * CIN];      // w*w_scale fp16, [co][tap][ci]

// ---------------- PTX helpers ----------------
__device__ __forceinline__ uint32_t smem_u32(const void* p) {
    uint32_t a;
    asm("{ .reg .u64 t; cvta.to.shared.u64 t, %1; cvt.u32.u64 %0, t; }" : "=r"(a) : "l"(p));
    return a;
}
__device__ __forceinline__ void cp16(uint32_t dst, const void* src, uint32_t srcsize) {
    asm volatile("cp.async.cg.shared.global [%0], [%1], 16, %2;"
                 :: "r"(dst), "l"(src), "r"(srcsize));
}
#define CP_COMMIT() asm volatile("cp.async.commit_group;" ::: "memory")
#define CP_WAIT2()  asm volatile("cp.async.wait_group 2;" ::: "memory")

__device__ __forceinline__ void ldm_x4(uint32_t r[4], uint32_t addr) {
    asm volatile("ldmatrix.sync.aligned.m8n8.x4.shared.b16 {%0,%1,%2,%3}, [%4];"
                 : "=r"(r[0]), "=r"(r[1]), "=r"(r[2]), "=r"(r[3]) : "r"(addr));
}
__device__ __forceinline__ void mma_f16(float c[4], const uint32_t a[4],
                                        uint32_t b0, uint32_t b1) {
    asm volatile(
        "mma.sync.aligned.m16n8k16.row.col.f32.f16.f16.f32 "
        "{%0,%1,%2,%3}, {%4,%5,%6,%7}, {%8,%9}, {%0,%1,%2,%3};"
        : "+f"(c[0]), "+f"(c[1]), "+f"(c[2]), "+f"(c[3])
        : "r"(a[0]), "r"(a[1]), "r"(a[2]), "r"(a[3]), "r"(b0), "r"(b1));
}
__device__ __forceinline__ float warp_sum(float v) {
#pragma unroll
    for (int o = 16; o > 0; o >>= 1)
        v += __shfl_xor_sync(0xFFFFFFFFu, v, o);
    return v;
}

// ---------------------------------------------------------------------------
// merged: weights*w_scale -> fp16 [co][tap][ci], plus wsq (sum of squares).
// grid = COUT, block = CIN
__global__ void k_wprep(const float* __restrict__ w) {
    int co = blockIdx.x, ci = threadIdx.x;
    const float ws = rsqrtf((float)(CIN * 9));
    const float* src = w + ((size_t)co * CIN + ci) * 9;
    float acc = 0.f;
#pragma unroll
    for (int tap = 0; tap < 9; tap++) {
        float v = src[tap];
        acc += v * v;
        g_wh[((size_t)co * 9 + tap) * CIN + ci] = __float2half(v * ws);
    }
    g_wsq[co * CIN + ci] = acc;
}

// ---------------------------------------------------------------------------
// s[n,c] = lin_scale * dot(style[n,:], style_w[c,:]) + style_b[c]
// warp-per-c, lane-coalesced reads.  grid = (N_, 16), block = 256 (8 warps x 4 c)
__global__ void k_style(const float* __restrict__ style,
                        const float* __restrict__ style_w,
                        const float* __restrict__ style_b) {
    __shared__ float sty[SDIM];
    const int n = blockIdx.x;
    const int t = threadIdx.x, lane = t & 31, wp = t >> 5;
    sty[t] = style[n * SDIM + t];
    sty[t + 256] = style[n * SDIM + t + 256];
    __syncthreads();
    const float lin_scale = rsqrtf((float)SDIM);
#pragma unroll
    for (int q = 0; q < 4; q++) {
        int c = blockIdx.y * 32 + wp * 4 + q;
        const float* wr = style_w + (size_t)c * SDIM;
        float acc = 0.f;
#pragma unroll
        for (int i = 0; i < SDIM / 32; i++)
            acc += sty[i * 32 + lane] * wr[i * 32 + lane];
        acc = warp_sum(acc);
        if (lane == 0) g_s[n * CIN + c] = acc * lin_scale + style_b[c];
    }
}

// ---------------------------------------------------------------------------
// demod[n,o] = rsqrt(ws^2 * dot(wsq[o,:], s[n,:]^2) + eps); warp-per-o.
// grid = (N_, 16), block = 256 (8 warps x 4 o)
__global__ void k_demod() {
    __shared__ float s2[CIN];
    const int n = blockIdx.x;
    const int t = threadIdx.x, lane = t & 31, wp = t >> 5;
    float a0 = g_s[n * CIN + t], a1 = g_s[n * CIN + t + 256];
    s2[t] = a0 * a0;
    s2[t + 256] = a1 * a1;
    __syncthreads();
    const float ws = rsqrtf((float)(CIN * 9));
#pragma unroll
    for (int q = 0; q < 4; q++) {
        int o = blockIdx.y * 32 + wp * 4 + q;
        const float* wr = g_wsq + (size_t)o * CIN;
        float acc = 0.f;
#pragma unroll
        for (int i = 0; i < CIN / 32; i++)
            acc += s2[i * 32 + lane] * wr[i * 32 + lane];
        acc = warp_sum(acc);
        if (lane == 0) g_dm[n * COUT + o] = rsqrtf(ws * ws * acc + EPSF);
    }
}

// ---------------------------------------------------------------------------
// modulated x -> NHWC fp16, vectorized transpose.  grid = (HH, N_), block 256
__global__ void k_xprep(const float* __restrict__ x) {
    __shared__ float tile[128][65];
    __shared__ float ss[CIN];
    const int y = blockIdx.x, n = blockIdx.y, t = threadIdx.x;
    ss[t] = g_s[n * CIN + t];
    ss[t + 256] = g_s[n * CIN + t + 256];
    __syncthreads();
    for (int cic = 0; cic < 4; cic++) {
        if (cic) __syncthreads();
        // read: 128 ci x 64 xx floats as float4 (coalesced along xx)
#pragma unroll
        for (int u = 0; u < 8; u++) {
            int idx = u * 256 + t;          // 0..2047
            int ci = idx >> 4;              // 0..127
            int x4 = idx & 15;              // float4 index along xx
            const float4 v = *(const float4*)
                &x[(((size_t)(n * CIN + cic * 128 + ci)) * HH + y) * WW + x4 * 4];
            float sc = ss[cic * 128 + ci];
            tile[ci][x4 * 4 + 0] = v.x * sc;
            tile[ci][x4 * 4 + 1] = v.y * sc;
            tile[ci][x4 * 4 + 2] = v.z * sc;
            tile[ci][x4 * 4 + 3] = v.w * sc;
        }
        __syncthreads();
        // write: per (xx, ci-group-of-8) a uint4 of 4 half2 (coalesced along ci)
#pragma unroll
        for (int u = 0; u < 4; u++) {
            int idx = u * 256 + t;          // 0..1023
            int cg = idx & 15;              // ci group (lanes fastest -> coalesced)
            int xx = idx >> 4;              // 0..63
            int ci = cg * 8;
            __half2 h[4];
#pragma unroll
            for (int q = 0; q < 4; q++)
                h[q] = __floats2half2_rn(tile[ci + 2 * q][xx], tile[ci + 2 * q + 1][xx]);
            size_t o = ((size_t)((n * HH + y) * WW + xx)) * CIN + cic * 128 + ci;
            *(uint4*)&g_xh[o] = *(const uint4*)h;
        }
    }
}

// ---------------------------------------------------------------------------
// Load one pipeline stage: A (128px x 32ci) + B (128co x 32ci).
__device__ __forceinline__ void load_stage(uint32_t sbase, int n, int y0, int co0,
                                           int j, int t) {
    const int tap = j >> 4;          // 0..8
    const int cic = j & 15;          // ci chunk 0..15
    const int dy = tap / 3 - 1, dx = tap % 3 - 1;
    // ---- A: 512 16B chunks ----
#pragma unroll
    for (int u = 0; u < 2; u++) {
        int id = u * 256 + t;
        int row = id >> 2;           // pixel 0..127
        int seg = id & 3;
        int ys = y0 + (row >> 6) + dy;
        int xs = (row & 63) + dx;
        bool ok = (ys >= 0) & (ys < HH) & (xs >= 0) & (xs < WW);
        int ysc = ok ? ys : 0, xsc = ok ? xs : 0;
        const __half* src =
            g_xh + ((size_t)((n * HH + ysc) * WW + xsc)) * CIN + cic * KCH + seg * 8;
        uint32_t dst = sbase + row * ROWB + seg * 16;
        cp16(dst, src, ok ? 16u : 0u);
    }
    // ---- B: 512 16B chunks ----
#pragma unroll
    for (int u = 0; u < 2; u++) {
        int id = u * 256 + t;
        int row = id >> 2;           // cout 0..127
        int seg = id & 3;
        const __half* src =
            g_wh + ((size_t)(co0 + row) * 9 + tap) * CIN + cic * KCH + seg * 8;
        uint32_t dst = sbase + ARR_B + row * ROWB + seg * 16;
        cp16(dst, src, 16u);
    }
}

// ---------------------------------------------------------------------------
// Implicit-GEMM modulated conv via fp16 mma.sync, single pass.
__global__ void __launch_bounds__(256, 2)
k_conv(float* __restrict__ out) {
    extern __shared__ __align__(16) char smem[];
    const uint32_t sb = smem_u32(smem);
    float* sdemod = (float*)(smem + STAGES * STAGE_B);

    const int t = threadIdx.x;
    const int lane = t & 31;
    const int w = t >> 5;
    const int warp_m = w & 3;          // 4 m-warps: 32 px each
    const int warp_n = w >> 2;         // 2 n-warps: 64 co each
    const int n = blockIdx.z;
    const int co0 = blockIdx.y * TILE_N;
    const int y0 = blockIdx.x * 2;

    if (t < TILE_N) sdemod[t] = g_dm[n * COUT + co0 + t];

    const uint32_t a_off =
        (uint32_t)((warp_m * 32 + (lane & 15)) * ROWB + (lane >> 4) * 16);
    // B is [n][k] k-contiguous == col-major B for mma row.col; NON-trans ldmatrix.
    const uint32_t b_off =
        (uint32_t)(ARR_B +
                   (warp_n * 64 + (lane & 7) + (lane >> 4) * 8) * ROWB +
                   ((lane >> 3) & 1) * 16);

    float acc[2][8][4];
#pragma unroll
    for (int mt = 0; mt < 2; mt++)
#pragma unroll
        for (int nt = 0; nt < 8; nt++)
#pragma unroll
            for (int q = 0; q < 4; q++) acc[mt][nt][q] = 0.f;

    // prologue: stages 0,1
    load_stage(sb + 0 * STAGE_B, n, y0, co0, 0, t);
    CP_COMMIT();
    load_stage(sb + 1 * STAGE_B, n, y0, co0, 1, t);
    CP_COMMIT();

    int st = 0;
    for (int j = 0; j < NITER; j++) {
        if (j + 2 < NITER) {
            int s2 = (j + 2) % STAGES;
            load_stage(sb + s2 * STAGE_B, n, y0, co0, j + 2, t);
        }
        CP_COMMIT();
        CP_WAIT2();
        __syncthreads();

        const uint32_t base = sb + st * STAGE_B;
#pragma unroll
        for (int ks = 0; ks < 2; ks++) {
            const uint32_t ko = ks * 32;
            uint32_t ah[2][4];
#pragma unroll
            for (int mt = 0; mt < 2; mt++)
                ldm_x4(ah[mt], base + a_off + mt * 16 * ROWB + ko);
            uint32_t bh[4][4];
#pragma unroll
            for (int p = 0; p < 4; p++)
                ldm_x4(bh[p], base + b_off + p * 16 * ROWB + ko);
#pragma unroll
            for (int mt = 0; mt < 2; mt++) {
#pragma unroll
                for (int nt = 0; nt < 8; nt++) {
                    const int p = nt >> 1, h = (nt & 1) * 2;
                    mma_f16(acc[mt][nt], ah[mt], bh[p][h], bh[p][h + 1]);
                }
            }
        }
        __syncthreads();
        st = (st + 1) % STAGES;
    }

    // ---- epilogue: demod + scatter to NCHW ----
    const int r0 = lane >> 2;
    const int c0 = (lane & 3) * 2;
#pragma unroll
    for (int mt = 0; mt < 2; mt++) {
#pragma unroll
        for (int nt = 0; nt < 8; nt++) {
            int col = warp_n * 64 + nt * 8 + c0;        // co - co0
            float d0 = sdemod[col], d1 = sdemod[col + 1];
#pragma unroll
            for (int half = 0; half < 2; half++) {
                int p = warp_m * 32 + mt * 16 + r0 + half * 8;   // pixel 0..127
                int y = y0 + (p >> 6);
                int xo = p & 63;
                size_t o = (((size_t)(n * COUT + co0 + col)) * HH + y) * WW + xo;
                out[o] = acc[mt][nt][half * 2] * d0;
                out[o + (size_t)HH * WW] = acc[mt][nt][half * 2 + 1] * d1;
            }
        }
    }
}

// ---------------------------------------------------------------------------
extern "C" void kernel_launch(void* const* d_in, const int* in_sizes, int n_in,
                              void* d_out, int out_size) {
    const float* x       = (const float*)d_in[0];   // [16,512,64,64]
    const float* style   = (const float*)d_in[1];   // [16,512]
    const float* weight  = (const float*)d_in[2];   // [512,512,3,3]
    const float* style_w = (const float*)d_in[3];   // [512,512]
    const float* style_b = (const float*)d_in[4];   // [512]
    float* out = (float*)d_out;                     // [16,512,64,64]

    k_wprep<<<COUT, CIN>>>(weight);                  // w fp16 + wsq (one pass)
    dim3 sg(N_, 16);
    k_style<<<sg, 256>>>(style, style_w, style_b);
    k_demod<<<sg, 256>>>();
    dim3 xg(HH, N_);
    k_xprep<<<xg, 256>>>(x);

    cudaFuncSetAttribute(k_conv, cudaFuncAttributeMaxDynamicSharedMemorySize, SMEM_TOTAL);
    dim3 grid(HH / 2, COUT / TILE_N, N_);            // (32 row-pairs, 4 co tiles, 16 n)
    k_conv<<<grid, 256, SMEM_TOTAL>>>(out);
}

// round 9
// speedup vs baseline: 13.6087x; 1.6475x over previous
#include <cuda_runtime.h>
#include <cuda_fp16.h>
#include <cstdint>

// ---------------- problem constants ----------------
#define N_    16
#define CIN   512
#define COUT  512
#define HH    64
#define WW    64
#define SDIM  512
#define EPSF  1e-8f
#define MTOT  (N_ * 32 * 32)       // 16384 winograd tiles

// ---------------- GEMM tiling ----------------
#define TILE_M 128
#define TILE_N 128
#define KCH    32                  // ci per k-chunk
#define NITER  (CIN / KCH)         // 16
#define STAGES 3
#define ROWB   80                  // padded smem row stride (bytes) for 64B rows
#define ARR_B  (128 * ROWB)
#define STAGE_B (2 * ARR_B)
#define SMEM_TOTAL (STAGES * STAGE_B)   // 61440

// ---------------- device scratch ----------------
__device__ float g_s[N_ * CIN];
__device__ float g_wsq[COUT * CIN];
__device__ float g_dm[N_ * COUT];
__device__ __half g_U[(size_t)16 * COUT * CIN];     // weight transform, [xi][co][ci]
__device__ __half g_V[(size_t)16 * MTOT * CIN];     // input transform,  [xi][m][ci]
__device__ float  g_M[(size_t)16 * COUT * MTOT];    // GEMM result,      [xi][co][m]

// ---------------- PTX helpers ----------------
__device__ __forceinline__ uint32_t smem_u32(const void* p) {
    uint32_t a;
    asm("{ .reg .u64 t; cvta.to.shared.u64 t, %1; cvt.u32.u64 %0, t; }" : "=r"(a) : "l"(p));
    return a;
}
__device__ __forceinline__ void cp16(uint32_t dst, const void* src) {
    asm volatile("cp.async.cg.shared.global [%0], [%1], 16;" :: "r"(dst), "l"(src));
}
#define CP_COMMIT() asm volatile("cp.async.commit_group;" ::: "memory")
#define CP_WAIT2()  asm volatile("cp.async.wait_group 2;" ::: "memory")

__device__ __forceinline__ void ldm_x4(uint32_t r[4], uint32_t addr) {
    asm volatile("ldmatrix.sync.aligned.m8n8.x4.shared.b16 {%0,%1,%2,%3}, [%4];"
                 : "=r"(r[0]), "=r"(r[1]), "=r"(r[2]), "=r"(r[3]) : "r"(addr));
}
__device__ __forceinline__ void mma_f16(float c[4], const uint32_t a[4],
                                        uint32_t b0, uint32_t b1) {
    asm volatile(
        "mma.sync.aligned.m16n8k16.row.col.f32.f16.f16.f32 "
        "{%0,%1,%2,%3}, {%4,%5,%6,%7}, {%8,%9}, {%0,%1,%2,%3};"
        : "+f"(c[0]), "+f"(c[1]), "+f"(c[2]), "+f"(c[3])
        : "r"(a[0]), "r"(a[1]), "r"(a[2]), "r"(a[3]), "r"(b0), "r"(b1));
}
__device__ __forceinline__ float warp_sum(float v) {
#pragma unroll
    for (int o = 16; o > 0; o >>= 1)
        v += __shfl_xor_sync(0xFFFFFFFFu, v, o);
    return v;
}

// ---------------------------------------------------------------------------
// U = G (w*ws) G^T  fp16 [xi][co][ci]; also wsq (raw w sum of squares).
// grid = COUT, block = CIN
__global__ void k_wprep(const float* __restrict__ w) {
    int co = blockIdx.x, ci = threadIdx.x;
    const float ws = rsqrtf((float)(CIN * 9));
    const float* src = w + ((size_t)co * CIN + ci) * 9;
    float g[9], acc = 0.f;
#pragma unroll
    for (int i = 0; i < 9; i++) { g[i] = src[i]; acc += g[i] * g[i]; }
    g_wsq[co * CIN + ci] = acc;
#pragma unroll
    for (int i = 0; i < 9; i++) g[i] *= ws;
    float tG[4][3];
#pragma unroll
    for (int c = 0; c < 3; c++) {
        tG[0][c] = g[c];
        tG[1][c] = 0.5f * (g[c] + g[3 + c] + g[6 + c]);
        tG[2][c] = 0.5f * (g[c] - g[3 + c] + g[6 + c]);
        tG[3][c] = g[6 + c];
    }
#pragma unroll
    for (int r = 0; r < 4; r++) {
        float u0 = tG[r][0];
        float u1 = 0.5f * (tG[r][0] + tG[r][1] + tG[r][2]);
        float u2 = 0.5f * (tG[r][0] - tG[r][1] + tG[r][2]);
        float u3 = tG[r][2];
        g_U[((size_t)(r * 4 + 0) * COUT + co) * CIN + ci] = __float2half(u0);
        g_U[((size_t)(r * 4 + 1) * COUT + co) * CIN + ci] = __float2half(u1);
        g_U[((size_t)(r * 4 + 2) * COUT + co) * CIN + ci] = __float2half(u2);
        g_U[((size_t)(r * 4 + 3) * COUT + co) * CIN + ci] = __float2half(u3);
    }
}

// ---------------------------------------------------------------------------
// s[n,c]: warp-per-c coalesced.  grid = (N_, 16), block = 256
__global__ void k_style(const float* __restrict__ style,
                        const float* __restrict__ style_w,
                        const float* __restrict__ style_b) {
    __shared__ float sty[SDIM];
    const int n = blockIdx.x;
    const int t = threadIdx.x, lane = t & 31, wp = t >> 5;
    sty[t] = style[n * SDIM + t];
    sty[t + 256] = style[n * SDIM + t + 256];
    __syncthreads();
    const float lin_scale = rsqrtf((float)SDIM);
#pragma unroll
    for (int q = 0; q < 4; q++) {
        int c = blockIdx.y * 32 + wp * 4 + q;
        const float* wr = style_w + (size_t)c * SDIM;
        float acc = 0.f;
#pragma unroll
        for (int i = 0; i < SDIM / 32; i++)
            acc += sty[i * 32 + lane] * wr[i * 32 + lane];
        acc = warp_sum(acc);
        if (lane == 0) g_s[n * CIN + c] = acc * lin_scale + style_b[c];
    }
}

// ---------------------------------------------------------------------------
// demod: warp-per-o.  grid = (N_, 16), block = 256
__global__ void k_demod() {
    __shared__ float s2[CIN];
    const int n = blockIdx.x;
    const int t = threadIdx.x, lane = t & 31, wp = t >> 5;
    float a0 = g_s[n * CIN + t], a1 = g_s[n * CIN + t + 256];
    s2[t] = a0 * a0;
    s2[t + 256] = a1 * a1;
    __syncthreads();
    const float ws = rsqrtf((float)(CIN * 9));
#pragma unroll
    for (int q = 0; q < 4; q++) {
        int o = blockIdx.y * 32 + wp * 4 + q;
        const float* wr = g_wsq + (size_t)o * CIN;
        float acc = 0.f;
#pragma unroll
        for (int i = 0; i < CIN / 32; i++)
            acc += s2[i * 32 + lane] * wr[i * 32 + lane];
        acc = warp_sum(acc);
        if (lane == 0) g_dm[n * COUT + o] = rsqrtf(ws * ws * acc + EPSF);
    }
}

// ---------------------------------------------------------------------------
// V = B^T (x*s) B  fp16 [xi][m][ci], from fp32 NCHW x directly.
// grid = (16 cig, N_ n, 2 tyh), block = 256
__global__ void k_vtrans(const float* __restrict__ x) {
    __shared__ float srow[4][66][33];   // [r][x+1][ci], padded conflict-free
    __shared__ float ssc[32];
    const int cig = blockIdx.x, n = blockIdx.y, tyh = blockIdx.z;
    const int t = threadIdx.x;

    if (t < 32) ssc[t] = g_s[n * CIN + cig * 32 + t];
    if (t < 256) {   // zero halo columns 0 and 65 (constant across ty)
        int r = t >> 6, side = (t >> 5) & 1, ci = t & 31;
        srow[r][side * 65][ci] = 0.f;
    }
    __syncthreads();

    for (int ty = tyh * 16; ty < tyh * 16 + 16; ty++) {
        // load 4 rows x 64 cols x 32 ci (float4 along x), modulated
#pragma unroll
        for (int u = 0; u < 8; u++) {
            int id = u * 256 + t;
            int xq = id & 15, r = (id >> 4) & 3, ci = id >> 6;
            int y = 2 * ty - 1 + r;
            float4 v = make_float4(0.f, 0.f, 0.f, 0.f);
            if (y >= 0 && y < HH)
                v = *(const float4*)&x[(((size_t)(n * CIN + cig * 32 + ci)) * HH + y) * WW + xq * 4];
            float sc = ssc[ci];
            srow[r][xq * 4 + 1][ci] = v.x * sc;
            srow[r][xq * 4 + 2][ci] = v.y * sc;
            srow[r][xq * 4 + 3][ci] = v.z * sc;
            srow[r][xq * 4 + 4][ci] = v.w * sc;
        }
        __syncthreads();
#pragma unroll
        for (int p = 0; p < 4; p++) {
            int tx = (t >> 5) + p * 8;
            int ci = t & 31;
            float d[4][4];
#pragma unroll
            for (int r = 0; r < 4; r++)
#pragma unroll
                for (int c = 0; c < 4; c++)
                    d[r][c] = srow[r][2 * tx + c][ci];
            float z[4][4];
#pragma unroll
            for (int c = 0; c < 4; c++) {
                z[0][c] = d[0][c] - d[2][c];
                z[1][c] = d[1][c] + d[2][c];
                z[2][c] = d[2][c] - d[1][c];
                z[3][c] = d[1][c] - d[3][c];
            }
            size_t mb = ((size_t)(n * 1024 + ty * 32 + tx)) * CIN + cig * 32 + ci;
#pragma unroll
            for (int i = 0; i < 4; i++) {
                float v0 = z[i][0] - z[i][2];
                float v1 = z[i][1] + z[i][2];
                float v2 = z[i][2] - z[i][1];
                float v3 = z[i][1] - z[i][3];
                g_V[(size_t)(i * 4 + 0) * (MTOT * CIN) + mb] = __float2half(v0);
                g_V[(size_t)(i * 4 + 1) * (MTOT * CIN) + mb] = __float2half(v1);
                g_V[(size_t)(i * 4 + 2) * (MTOT * CIN) + mb] = __float2half(v2);
                g_V[(size_t)(i * 4 + 3) * (MTOT * CIN) + mb] = __float2half(v3);
            }
        }
        __syncthreads();
    }
}

// ---------------------------------------------------------------------------
// Stage loader: A = V[xi][m0..+128][32ci], B = U[xi][co0..+128][32ci]
__device__ __forceinline__ void load_stage(uint32_t sbase, int xi, int m0, int co0,
                                           int cic, int t) {
#pragma unroll
    for (int u = 0; u < 2; u++) {
        int id = u * 256 + t;
        int row = id >> 2, seg = id & 3;
        const __half* src = g_V + ((size_t)xi * MTOT + m0 + row) * CIN + cic * KCH + seg * 8;
        cp16(sbase + row * ROWB + seg * 16, src);
    }
#pragma unroll
    for (int u = 0; u < 2; u++) {
        int id = u * 256 + t;
        int row = id >> 2, seg = id & 3;
        const __half* src = g_U + ((size_t)xi * COUT + co0 + row) * CIN + cic * KCH + seg * 8;
        cp16(sbase + ARR_B + row * ROWB + seg * 16, src);
    }
}

// ---------------------------------------------------------------------------
// Winograd-domain GEMM: M[xi][co][m] += V[xi][m][ci] * U[xi][co][ci]
// grid = (MTOT/128, COUT/128, 16), block = 256
__global__ void __launch_bounds__(256, 2)
k_gemm() {
    extern __shared__ __align__(16) char smem[];
    const uint32_t sb = smem_u32(smem);

    const int t = threadIdx.x;
    const int lane = t & 31;
    const int w = t >> 5;
    const int warp_m = w & 3;
    const int warp_n = w >> 2;
    const int m0 = blockIdx.x * TILE_M;
    const int co0 = blockIdx.y * TILE_N;
    const int xi = blockIdx.z;

    const uint32_t a_off =
        (uint32_t)((warp_m * 32 + (lane & 15)) * ROWB + (lane >> 4) * 16);
    const uint32_t b_off =
        (uint32_t)(ARR_B +
                   (warp_n * 64 + (lane & 7) + (lane >> 4) * 8) * ROWB +
                   ((lane >> 3) & 1) * 16);

    float acc[2][8][4];
#pragma unroll
    for (int mt = 0; mt < 2; mt++)
#pragma unroll
        for (int nt = 0; nt < 8; nt++)
#pragma unroll
            for (int q = 0; q < 4; q++) acc[mt][nt][q] = 0.f;

    load_stage(sb + 0 * STAGE_B, xi, m0, co0, 0, t);
    CP_COMMIT();
    load_stage(sb + 1 * STAGE_B, xi, m0, co0, 1, t);
    CP_COMMIT();

    int st = 0;
    for (int j = 0; j < NITER; j++) {
        if (j + 2 < NITER) {
            int s2 = (j + 2) % STAGES;
            load_stage(sb + s2 * STAGE_B, xi, m0, co0, j + 2, t);
        }
        CP_COMMIT();
        CP_WAIT2();
        __syncthreads();

        const uint32_t base = sb + st * STAGE_B;
#pragma unroll
        for (int ks = 0; ks < 2; ks++) {
            const uint32_t ko = ks * 32;
            uint32_t ah[2][4];
#pragma unroll
            for (int mt = 0; mt < 2; mt++)
                ldm_x4(ah[mt], base + a_off + mt * 16 * ROWB + ko);
            uint32_t bh[4][4];
#pragma unroll
            for (int p = 0; p < 4; p++)
                ldm_x4(bh[p], base + b_off + p * 16 * ROWB + ko);
#pragma unroll
            for (int mt = 0; mt < 2; mt++) {
#pragma unroll
                for (int nt = 0; nt < 8; nt++) {
                    const int p = nt >> 1, h = (nt & 1) * 2;
                    mma_f16(acc[mt][nt], ah[mt], bh[p][h], bh[p][h + 1]);
                }
            }
        }
        __syncthreads();
        st = (st + 1) % STAGES;
    }

    // epilogue: direct fp32 store, sector-aligned (8 consecutive m per col group)
#pragma unroll
    for (int mt = 0; mt < 2; mt++) {
#pragma unroll
        for (int nt = 0; nt < 8; nt++) {
            int r = warp_m * 32 + mt * 16 + (lane >> 2);
            int c = warp_n * 64 + nt * 8 + (lane & 3) * 2;
            size_t b0 = ((size_t)xi * COUT + co0 + c) * MTOT + m0;
            g_M[b0 + r] = acc[mt][nt][0];
            g_M[b0 + MTOT + r] = acc[mt][nt][1];
            g_M[b0 + r + 8] = acc[mt][nt][2];
            g_M[b0 + MTOT + r + 8] = acc[mt][nt][3];
        }
    }
}

// ---------------------------------------------------------------------------
// Y = A^T M A, * demod, scatter to NCHW.  grid = (COUT, N_), block = 256,
// dynamic smem 64KB: sm[xi][tile] fp32 for this (n, co).
__global__ void k_ytrans(float* __restrict__ out) {
    extern __shared__ __align__(16) float sm[];   // [16][1024]
    const int co = blockIdx.x, n = blockIdx.y;
    const int t = threadIdx.x;

#pragma unroll
    for (int u = 0; u < 16; u++) {
        int id = u * 256 + t;                 // float4 index: xi*256 + f4
        int xi = id >> 8, f4 = id & 255;
        ((float4*)sm)[id] = *(const float4*)
            &g_M[((size_t)xi * COUT + co) * MTOT + (size_t)n * 1024 + f4 * 4];
    }
    __syncthreads();

    const float dm = g_dm[n * COUT + co];
#pragma unroll
    for (int p = 0; p < 4; p++) {
        int tile = p * 256 + t;
        int ty = tile >> 5, tx = tile & 31;
        float m[4][4];
#pragma unroll
        for (int xi = 0; xi < 16; xi++)
            m[xi >> 2][xi & 3] = sm[xi * 1024 + tile];
        float z[2][4];
#pragma unroll
        for (int c = 0; c < 4; c++) {
            z[0][c] = m[0][c] + m[1][c] + m[2][c];
            z[1][c] = m[1][c] - m[2][c] - m[3][c];
        }
        size_t ob = (((size_t)(n * COUT + co)) * HH + 2 * ty) * WW + 2 * tx;
        float2 r0 = make_float2((z[0][0] + z[0][1] + z[0][2]) * dm,
                                (z[0][1] - z[0][2] - z[0][3]) * dm);
        float2 r1 = make_float2((z[1][0] + z[1][1] + z[1][2]) * dm,
                                (z[1][1] - z[1][2] - z[1][3]) * dm);
        *(float2*)&out[ob] = r0;
        *(float2*)&out[ob + WW] = r1;
    }
}

// ---------------------------------------------------------------------------
extern "C" void kernel_launch(void* const* d_in, const int* in_sizes, int n_in,
                              void* d_out, int out_size) {
    const float* x       = (const float*)d_in[0];   // [16,512,64,64]
    const float* style   = (const float*)d_in[1];   // [16,512]
    const float* weight  = (const float*)d_in[2];   // [512,512,3,3]
    const float* style_w = (const float*)d_in[3];   // [512,512]
    const float* style_b = (const float*)d_in[4];   // [512]
    float* out = (float*)d_out;                     // [16,512,64,64]

    k_wprep<<<COUT, CIN>>>(weight);
    dim3 sg(N_, 16);
    k_style<<<sg, 256>>>(style, style_w, style_b);
    k_demod<<<sg, 256>>>();
    dim3 vg(16, N_, 2);
    k_vtrans<<<vg, 256>>>(x);

    cudaFuncSetAttribute(k_gemm, cudaFuncAttributeMaxDynamicSharedMemorySize, SMEM_TOTAL);
    dim3 gg(MTOT / TILE_M, COUT / TILE_N, 16);      // (128, 4, 16)
    k_gemm<<<gg, 256, SMEM_TOTAL>>>();

    cudaFuncSetAttribute(k_ytrans, cudaFuncAttributeMaxDynamicSharedMemorySize, 65536);
    dim3 yg(COUT, N_);
    k_ytrans<<<yg, 256, 65536>>>(out);
}

// round 11
// speedup vs baseline: 14.7773x; 1.0859x over previous
#include <cuda_runtime.h>
#include <cuda_fp16.h>
#include <cstdint>

// ---------------- problem constants ----------------
#define N_    16
#define CIN   512
#define COUT  512
#define HH    64
#define WW    64
#define SDIM  512
#define EPSF  1e-8f
#define MTOT  (N_ * 32 * 32)       // 16384 winograd tiles

// ---------------- GEMM tiling ----------------
#define TILE_M 128
#define TILE_N 128
#define KCH    32                  // ci per k-chunk
#define NITER  (CIN / KCH)         // 16
#define STAGES 3
#define ROWB   80                  // padded smem row stride (bytes) for 64B rows
#define ARR_B  (128 * ROWB)
#define STAGE_B (2 * ARR_B)
#define SMEM_TOTAL (STAGES * STAGE_B)   // 61440

// ---------------- device scratch ----------------
__device__ float g_s[N_ * CIN];
__device__ float g_wsq[COUT * CIN];
__device__ float g_dm[N_ * COUT];
__device__ __half g_U[(size_t)16 * COUT * CIN];     // weight transform, [xi][co][ci]
__device__ __half g_V[(size_t)16 * MTOT * CIN];     // input transform,  [xi][m][ci]
__device__ __half g_M[(size_t)16 * COUT * MTOT];    // GEMM result fp16, [xi][co][m]

// ---------------- PTX helpers ----------------
__device__ __forceinline__ uint32_t smem_u32(const void* p) {
    uint32_t a;
    asm("{ .reg .u64 t; cvta.to.shared.u64 t, %1; cvt.u32.u64 %0, t; }" : "=r"(a) : "l"(p));
    return a;
}
__device__ __forceinline__ void cp16(uint32_t dst, const void* src) {
    asm volatile("cp.async.cg.shared.global [%0], [%1], 16;" :: "r"(dst), "l"(src));
}
#define CP_COMMIT() asm volatile("cp.async.commit_group;" ::: "memory")
#define CP_WAIT2()  asm volatile("cp.async.wait_group 2;" ::: "memory")

__device__ __forceinline__ void ldm_x4(uint32_t r[4], uint32_t addr) {
    asm volatile("ldmatrix.sync.aligned.m8n8.x4.shared.b16 {%0,%1,%2,%3}, [%4];"
                 : "=r"(r[0]), "=r"(r[1]), "=r"(r[2]), "=r"(r[3]) : "r"(addr));
}
__device__ __forceinline__ void mma_f16(float c[4], const uint32_t a[4],
                                        uint32_t b0, uint32_t b1) {
    asm volatile(
        "mma.sync.aligned.m16n8k16.row.col.f32.f16.f16.f32 "
        "{%0,%1,%2,%3}, {%4,%5,%6,%7}, {%8,%9}, {%0,%1,%2,%3};"
        : "+f"(c[0]), "+f"(c[1]), "+f"(c[2]), "+f"(c[3])
        : "r"(a[0]), "r"(a[1]), "r"(a[2]), "r"(a[3]), "r"(b0), "r"(b1));
}
__device__ __forceinline__ float warp_sum(float v) {
#pragma unroll
    for (int o = 16; o > 0; o >>= 1)
        v += __shfl_xor_sync(0xFFFFFFFFu, v, o);
    return v;
}

// ---------------------------------------------------------------------------
// U = G (w*ws) G^T  fp16 [xi][co][ci]; also wsq (raw w sum of squares).
__global__ void k_wprep(const float* __restrict__ w) {
    int co = blockIdx.x, ci = threadIdx.x;
    const float ws = rsqrtf((float)(CIN * 9));
    const float* src = w + ((size_t)co * CIN + ci) * 9;
    float g[9], acc = 0.f;
#pragma unroll
    for (int i = 0; i < 9; i++) { g[i] = src[i]; acc += g[i] * g[i]; }
    g_wsq[co * CIN + ci] = acc;
#pragma unroll
    for (int i = 0; i < 9; i++) g[i] *= ws;
    float tG[4][3];
#pragma unroll
    for (int c = 0; c < 3; c++) {
        tG[0][c] = g[c];
        tG[1][c] = 0.5f * (g[c] + g[3 + c] + g[6 + c]);
        tG[2][c] = 0.5f * (g[c] - g[3 + c] + g[6 + c]);
        tG[3][c] = g[6 + c];
    }
#pragma unroll
    for (int r = 0; r < 4; r++) {
        float u0 = tG[r][0];
        float u1 = 0.5f * (tG[r][0] + tG[r][1] + tG[r][2]);
        float u2 = 0.5f * (tG[r][0] - tG[r][1] + tG[r][2]);
        float u3 = tG[r][2];
        g_U[((size_t)(r * 4 + 0) * COUT + co) * CIN + ci] = __float2half(u0);
        g_U[((size_t)(r * 4 + 1) * COUT + co) * CIN + ci] = __float2half(u1);
        g_U[((size_t)(r * 4 + 2) * COUT + co) * CIN + ci] = __float2half(u2);
        g_U[((size_t)(r * 4 + 3) * COUT + co) * CIN + ci] = __float2half(u3);
    }
}

// ---------------------------------------------------------------------------
__global__ void k_style(const float* __restrict__ style,
                        const float* __restrict__ style_w,
                        const float* __restrict__ style_b) {
    __shared__ float sty[SDIM];
    const int n = blockIdx.x;
    const int t = threadIdx.x, lane = t & 31, wp = t >> 5;
    sty[t] = style[n * SDIM + t];
    sty[t + 256] = style[n * SDIM + t + 256];
    __syncthreads();
    const float lin_scale = rsqrtf((float)SDIM);
#pragma unroll
    for (int q = 0; q < 4; q++) {
        int c = blockIdx.y * 32 + wp * 4 + q;
        const float* wr = style_w + (size_t)c * SDIM;
        float acc = 0.f;
#pragma unroll
        for (int i = 0; i < SDIM / 32; i++)
            acc += sty[i * 32 + lane] * wr[i * 32 + lane];
        acc = warp_sum(acc);
        if (lane == 0) g_s[n * CIN + c] = acc * lin_scale + style_b[c];
    }
}

// ---------------------------------------------------------------------------
__global__ void k_demod() {
    __shared__ float s2[CIN];
    const int n = blockIdx.x;
    const int t = threadIdx.x, lane = t & 31, wp = t >> 5;
    float a0 = g_s[n * CIN + t], a1 = g_s[n * CIN + t + 256];
    s2[t] = a0 * a0;
    s2[t + 256] = a1 * a1;
    __syncthreads();
    const float ws = rsqrtf((float)(CIN * 9));
#pragma unroll
    for (int q = 0; q < 4; q++) {
        int o = blockIdx.y * 32 + wp * 4 + q;
        const float* wr = g_wsq + (size_t)o * CIN;
        float acc = 0.f;
#pragma unroll
        for (int i = 0; i < CIN / 32; i++)
            acc += s2[i * 32 + lane] * wr[i * 32 + lane];
        acc = warp_sum(acc);
        if (lane == 0) g_dm[n * COUT + o] = rsqrtf(ws * ws * acc + EPSF);
    }
}

// ---------------------------------------------------------------------------
// V = B^T (x*s) B  fp16 [xi][m][ci], rolling 4-row ring buffer (each x row
// loaded once).  grid = (16 cig, N_ n, 4 strips of 8 ty), block = 256
__global__ void k_vtrans(const float* __restrict__ x) {
    __shared__ float srow[4][66][33];   // ring slot = (y+1)&3; [x+1][ci] padded
    __shared__ float ssc[32];
    const int cig = blockIdx.x, n = blockIdx.y;
    const int ty0 = blockIdx.z * 8;
    const int t = threadIdx.x;

    if (t < 32) ssc[t] = g_s[n * CIN + cig * 32 + t];
    {   // zero halo columns 0 and 65 in all 4 slots (256 threads exactly)
        int r = t >> 6, side = (t >> 5) & 1, ci = t & 31;
        srow[r][side * 65][ci] = 0.f;
    }
    __syncthreads();   // ssc + halo visible BEFORE any scaled fill (R10 bug fix)

    const float* xb = x + ((size_t)(n * CIN + cig * 32)) * HH * WW;

    // initial fill: rows y = 2*ty0-1 .. 2*ty0+2  (4 rows, 2 float4/thread/row)
#pragma unroll
    for (int rr = 0; rr < 4; rr++) {
        int y = 2 * ty0 - 1 + rr;
        int slot = (y + 1) & 3;
        int xq = t & 15, ci = t >> 4;                 // ci 0..15 (+16 in half 1)
#pragma unroll
        for (int half = 0; half < 2; half++) {
            int cih = ci + half * 16;
            float4 v = make_float4(0.f, 0.f, 0.f, 0.f);
            if (y >= 0 && y < HH)
                v = *(const float4*)&xb[((size_t)cih * HH + y) * WW + xq * 4];
            float sc = ssc[cih];
            srow[slot][xq * 4 + 1][cih] = v.x * sc;
            srow[slot][xq * 4 + 2][cih] = v.y * sc;
            srow[slot][xq * 4 + 3][cih] = v.z * sc;
            srow[slot][xq * 4 + 4][cih] = v.w * sc;
        }
    }
    __syncthreads();

    for (int ty = ty0; ty < ty0 + 8; ty++) {
        // ---- transform: each thread does 4 tile-columns for its ci ----
#pragma unroll
        for (int p = 0; p < 4; p++) {
            int tx = (t >> 5) + p * 8;
            int ci = t & 31;
            float d[4][4];
#pragma unroll
            for (int r = 0; r < 4; r++) {
                int slot = (2 * ty + r) & 3;          // y = 2ty-1+r -> (y+1)&3
#pragma unroll
                for (int c = 0; c < 4; c++)
                    d[r][c] = srow[slot][2 * tx + c][ci];
            }
            float z[4][4];
#pragma unroll
            for (int c = 0; c < 4; c++) {
                z[0][c] = d[0][c] - d[2][c];
                z[1][c] = d[1][c] + d[2][c];
                z[2][c] = d[2][c] - d[1][c];
                z[3][c] = d[1][c] - d[3][c];
            }
            size_t mb = ((size_t)(n * 1024 + ty * 32 + tx)) * CIN + cig * 32 + ci;
#pragma unroll
            for (int i = 0; i < 4; i++) {
                float v0 = z[i][0] - z[i][2];
                float v1 = z[i][1] + z[i][2];
                float v2 = z[i][2] - z[i][1];
                float v3 = z[i][1] - z[i][3];
                g_V[(size_t)(i * 4 + 0) * (MTOT * CIN) + mb] = __float2half(v0);
                g_V[(size_t)(i * 4 + 1) * (MTOT * CIN) + mb] = __float2half(v1);
                g_V[(size_t)(i * 4 + 2) * (MTOT * CIN) + mb] = __float2half(v2);
                g_V[(size_t)(i * 4 + 3) * (MTOT * CIN) + mb] = __float2half(v3);
            }
        }
        if (ty + 1 < ty0 + 8) {
            __syncthreads();   // transform reads done before slot overwrite
            // ---- load 2 new rows: y = 2ty+3, 2ty+4 (1024 float4 total) ----
#pragma unroll
            for (int u = 0; u < 4; u++) {
                int id = u * 256 + t;                 // 0..1023
                int rr = id >> 9;                     // 0,1
                int rem = id & 511;
                int xq = rem & 15, ci = rem >> 4;
                int y = 2 * ty + 3 + rr;
                int slot = (y + 1) & 3;
                float4 v = make_float4(0.f, 0.f, 0.f, 0.f);
                if (y < HH)
                    v = *(const float4*)&xb[((size_t)ci * HH + y) * WW + xq * 4];
                float sc = ssc[ci];
                srow[slot][xq * 4 + 1][ci] = v.x * sc;
                srow[slot][xq * 4 + 2][ci] = v.y * sc;
                srow[slot][xq * 4 + 3][ci] = v.z * sc;
                srow[slot][xq * 4 + 4][ci] = v.w * sc;
            }
            __syncthreads();
        }
    }
}

// ---------------------------------------------------------------------------
// Stage loader: A = V[xi][m0..+128][32ci], B = U[xi][co0..+128][32ci]
__device__ __forceinline__ void load_stage(uint32_t sbase, int xi, int m0, int co0,
                                           int cic, int t) {
#pragma unroll
    for (int u = 0; u < 2; u++) {
        int id = u * 256 + t;
        int row = id >> 2, seg = id & 3;
        const __half* src = g_V + ((size_t)xi * MTOT + m0 + row) * CIN + cic * KCH + seg * 8;
        cp16(sbase + row * ROWB + seg * 16, src);
    }
#pragma unroll
    for (int u = 0; u < 2; u++) {
        int id = u * 256 + t;
        int row = id >> 2, seg = id & 3;
        const __half* src = g_U + ((size_t)xi * COUT + co0 + row) * CIN + cic * KCH + seg * 8;
        cp16(sbase + ARR_B + row * ROWB + seg * 16, src);
    }
}

// ---------------------------------------------------------------------------
// Winograd-domain GEMM: M[xi][co][m] = V[xi][m][ci] * U[xi][co][ci], fp16 out.
__global__ void __launch_bounds__(256, 2)
k_gemm() {
    extern __shared__ __align__(16) char smem[];
    const uint32_t sb = smem_u32(smem);

    const int t = threadIdx.x;
    const int lane = t & 31;
    const int w = t >> 5;
    const int warp_m = w & 3;
    const int warp_n = w >> 2;
    const int m0 = blockIdx.x * TILE_M;
    const int co0 = blockIdx.y * TILE_N;
    const int xi = blockIdx.z;

    const uint32_t a_off =
        (uint32_t)((warp_m * 32 + (lane & 15)) * ROWB + (lane >> 4) * 16);
    const uint32_t b_off =
        (uint32_t)(ARR_B +
                   (warp_n * 64 + (lane & 7) + (lane >> 4) * 8) * ROWB +
                   ((lane >> 3) & 1) * 16);

    float acc[2][8][4];
#pragma unroll
    for (int mt = 0; mt < 2; mt++)
#pragma unroll
        for (int nt = 0; nt < 8; nt++)
#pragma unroll
            for (int q = 0; q < 4; q++) acc[mt][nt][q] = 0.f;

    load_stage(sb + 0 * STAGE_B, xi, m0, co0, 0, t);
    CP_COMMIT();
    load_stage(sb + 1 * STAGE_B, xi, m0, co0, 1, t);
    CP_COMMIT();

    int st = 0;
    for (int j = 0; j < NITER; j++) {
        if (j + 2 < NITER) {
            int s2 = (j + 2) % STAGES;
            load_stage(sb + s2 * STAGE_B, xi, m0, co0, j + 2, t);
        }
        CP_COMMIT();
        CP_WAIT2();
        __syncthreads();

        const uint32_t base = sb + st * STAGE_B;
#pragma unroll
        for (int ks = 0; ks < 2; ks++) {
            const uint32_t ko = ks * 32;
            uint32_t ah[2][4];
#pragma unroll
            for (int mt = 0; mt < 2; mt++)
                ldm_x4(ah[mt], base + a_off + mt * 16 * ROWB + ko);
            uint32_t bh[4][4];
#pragma unroll
            for (int p = 0; p < 4; p++)
                ldm_x4(bh[p], base + b_off + p * 16 * ROWB + ko);
#pragma unroll
            for (int mt = 0; mt < 2; mt++) {
#pragma unroll
                for (int nt = 0; nt < 8; nt++) {
                    const int p = nt >> 1, h = (nt & 1) * 2;
                    mma_f16(acc[mt][nt], ah[mt], bh[p][h], bh[p][h + 1]);
                }
            }
        }
        __syncthreads();
        st = (st + 1) % STAGES;
    }

    // epilogue: fp16 store (byte-granular, no cross-thread word races)
#pragma unroll
    for (int mt = 0; mt < 2; mt++) {
#pragma unroll
        for (int nt = 0; nt < 8; nt++) {
            int r = warp_m * 32 + mt * 16 + (lane >> 2);
            int c = warp_n * 64 + nt * 8 + (lane & 3) * 2;
            size_t b0 = ((size_t)xi * COUT + co0 + c) * MTOT + m0;
            g_M[b0 + r] = __float2half(acc[mt][nt][0]);
            g_M[b0 + MTOT + r] = __float2half(acc[mt][nt][1]);
            g_M[b0 + r + 8] = __float2half(acc[mt][nt][2]);
            g_M[b0 + MTOT + r + 8] = __float2half(acc[mt][nt][3]);
        }
    }
}

// ---------------------------------------------------------------------------
// Y = A^T M A, * demod, scatter to NCHW.  grid = (COUT, N_), block = 256,
// dynamic smem 32KB: sm[xi][tile] fp16 for this (n, co).
__global__ void k_ytrans(float* __restrict__ out) {
    extern __shared__ __align__(16) __half sm[];   // [16][1024]
    const int co = blockIdx.x, n = blockIdx.y;
    const int t = threadIdx.x;

#pragma unroll
    for (int u = 0; u < 8; u++) {
        int id = u * 256 + t;                 // uint4 index: 8 halfs each
        int xi = id >> 7, h8 = id & 127;
        ((uint4*)sm)[id] = *(const uint4*)
            &g_M[((size_t)xi * COUT + co) * MTOT + (size_t)n * 1024 + h8 * 8];
    }
    __syncthreads();

    const float dm = g_dm[n * COUT + co];
#pragma unroll
    for (int p = 0; p < 4; p++) {
        int tile = p * 256 + t;
        int ty = tile >> 5, tx = tile & 31;
        float m[4][4];
#pragma unroll
        for (int xi = 0; xi < 16; xi++)
            m[xi >> 2][xi & 3] = __half2float(sm[xi * 1024 + tile]);
        float z[2][4];
#pragma unroll
        for (int c = 0; c < 4; c++) {
            z[0][c] = m[0][c] + m[1][c] + m[2][c];
            z[1][c] = m[1][c] - m[2][c] - m[3][c];
        }
        size_t ob = (((size_t)(n * COUT + co)) * HH + 2 * ty) * WW + 2 * tx;
        float2 r0 = make_float2((z[0][0] + z[0][1] + z[0][2]) * dm,
                                (z[0][1] - z[0][2] - z[0][3]) * dm);
        float2 r1 = make_float2((z[1][0] + z[1][1] + z[1][2]) * dm,
                                (z[1][1] - z[1][2] - z[1][3]) * dm);
        *(float2*)&out[ob] = r0;
        *(float2*)&out[ob + WW] = r1;
    }
}

// ---------------------------------------------------------------------------
extern "C" void kernel_launch(void* const* d_in, const int* in_sizes, int n_in,
                              void* d_out, int out_size) {
    const float* x       = (const float*)d_in[0];   // [16,512,64,64]
    const float* style   = (const float*)d_in[1];   // [16,512]
    const float* weight  = (const float*)d_in[2];   // [512,512,3,3]
    const float* style_w = (const float*)d_in[3];   // [512,512]
    const float* style_b = (const float*)d_in[4];   // [512]
    float* out = (float*)d_out;                     // [16,512,64,64]

    k_wprep<<<COUT, CIN>>>(weight);
    dim3 sg(N_, 16);
    k_style<<<sg, 256>>>(style, style_w, style_b);
    k_demod<<<sg, 256>>>();
    dim3 vg(16, N_, 4);
    k_vtrans<<<vg, 256>>>(x);

    cudaFuncSetAttribute(k_gemm, cudaFuncAttributeMaxDynamicSharedMemorySize, SMEM_TOTAL);
    dim3 gg(MTOT / TILE_M, COUT / TILE_N, 16);      // (128, 4, 16)
    k_gemm<<<gg, 256, SMEM_TOTAL>>>();

    cudaFuncSetAttribute(k_ytrans, cudaFuncAttributeMaxDynamicSharedMemorySize, 32768);
    dim3 yg(COUT, N_);
    k_ytrans<<<yg, 256, 32768>>>(out);
}

// round 12
// speedup vs baseline: 14.8367x; 1.0040x over previous
#include <cuda_runtime.h>
#include <cuda_fp16.h>
#include <cstdint>

// ---------------- problem constants ----------------
#define N_    16
#define CIN   512
#define COUT  512
#define HH    64
#define WW    64
#define SDIM  512
#define EPSF  1e-8f
#define MTOT  (N_ * 32 * 32)       // 16384 winograd tiles

// ---------------- GEMM tiling ----------------
#define TILE_M 128
#define TILE_N 128
#define KCH    32                  // ci per k-chunk
#define NITER  (CIN / KCH)         // 16
#define STAGES 3
#define ROWB   80                  // padded smem row stride (bytes) for 64B rows
#define ARR_B  (128 * ROWB)
#define STAGE_B (2 * ARR_B)
#define SMEM_TOTAL (STAGES * STAGE_B)   // 61440

// ---------------- device scratch ----------------
__device__ float g_s[N_ * CIN];
__device__ float g_wsq[COUT * CIN];
__device__ float g_dm[N_ * COUT];
__device__ __half g_U[(size_t)16 * COUT * CIN];     // weight transform, [xi][co][ci]
__device__ __half g_V[(size_t)16 * MTOT * CIN];     // input transform,  [xi][m][ci]
__device__ __half g_M[(size_t)16 * COUT * MTOT];    // GEMM result fp16, [xi][co][m]

// ---------------- PTX helpers ----------------
__device__ __forceinline__ uint32_t smem_u32(const void* p) {
    uint32_t a;
    asm("{ .reg .u64 t; cvta.to.shared.u64 t, %1; cvt.u32.u64 %0, t; }" : "=r"(a) : "l"(p));
    return a;
}
__device__ __forceinline__ void cp16(uint32_t dst, const void* src) {
    asm volatile("cp.async.cg.shared.global [%0], [%1], 16;" :: "r"(dst), "l"(src));
}
#define CP_COMMIT() asm volatile("cp.async.commit_group;" ::: "memory")
#define CP_WAIT2()  asm volatile("cp.async.wait_group 2;" ::: "memory")

__device__ __forceinline__ void ldm_x4(uint32_t r[4], uint32_t addr) {
    asm volatile("ldmatrix.sync.aligned.m8n8.x4.shared.b16 {%0,%1,%2,%3}, [%4];"
                 : "=r"(r[0]), "=r"(r[1]), "=r"(r[2]), "=r"(r[3]) : "r"(addr));
}
__device__ __forceinline__ void mma_f16(float c[4], const uint32_t a[4],
                                        uint32_t b0, uint32_t b1) {
    asm volatile(
        "mma.sync.aligned.m16n8k16.row.col.f32.f16.f16.f32 "
        "{%0,%1,%2,%3}, {%4,%5,%6,%7}, {%8,%9}, {%0,%1,%2,%3};"
        : "+f"(c[0]), "+f"(c[1]), "+f"(c[2]), "+f"(c[3])
        : "r"(a[0]), "r"(a[1]), "r"(a[2]), "r"(a[3]), "r"(b0), "r"(b1));
}
__device__ __forceinline__ float warp_sum(float v) {
#pragma unroll
    for (int o = 16; o > 0; o >>= 1)
        v += __shfl_xor_sync(0xFFFFFFFFu, v, o);
    return v;
}
__device__ __forceinline__ float4 f4add(float4 a, float4 b) {
    return make_float4(a.x + b.x, a.y + b.y, a.z + b.z, a.w + b.w);
}
__device__ __forceinline__ float4 f4sub(float4 a, float4 b) {
    return make_float4(a.x - b.x, a.y - b.y, a.z - b.z, a.w - b.w);
}

// ---------------------------------------------------------------------------
// U = G (w*ws) G^T  fp16 [xi][co][ci]; also wsq.  Coalesced via smem staging.
// grid = COUT, block = 256
__global__ void k_wprep(const float* __restrict__ w) {
    __shared__ float wsm[CIN * 9];   // 18 KB
    const int co = blockIdx.x, t = threadIdx.x;
    const float4* src4 = (const float4*)(w + (size_t)co * CIN * 9);
#pragma unroll
    for (int i = t; i < CIN * 9 / 4; i += 256) ((float4*)wsm)[i] = src4[i];
    __syncthreads();
    const float ws = rsqrtf((float)(CIN * 9));
#pragma unroll
    for (int cq = 0; cq < 2; cq++) {
        int ci = cq * 256 + t;
        float g[9], acc = 0.f;
#pragma unroll
        for (int i = 0; i < 9; i++) { g[i] = wsm[ci * 9 + i]; acc += g[i] * g[i]; }
        g_wsq[co * CIN + ci] = acc;
#pragma unroll
        for (int i = 0; i < 9; i++) g[i] *= ws;
        float tG[4][3];
#pragma unroll
        for (int c = 0; c < 3; c++) {
            tG[0][c] = g[c];
            tG[1][c] = 0.5f * (g[c] + g[3 + c] + g[6 + c]);
            tG[2][c] = 0.5f * (g[c] - g[3 + c] + g[6 + c]);
            tG[3][c] = g[6 + c];
        }
#pragma unroll
        for (int r = 0; r < 4; r++) {
            float u0 = tG[r][0];
            float u1 = 0.5f * (tG[r][0] + tG[r][1] + tG[r][2]);
            float u2 = 0.5f * (tG[r][0] - tG[r][1] + tG[r][2]);
            float u3 = tG[r][2];
            g_U[((size_t)(r * 4 + 0) * COUT + co) * CIN + ci] = __float2half(u0);
            g_U[((size_t)(r * 4 + 1) * COUT + co) * CIN + ci] = __float2half(u1);
            g_U[((size_t)(r * 4 + 2) * COUT + co) * CIN + ci] = __float2half(u2);
            g_U[((size_t)(r * 4 + 3) * COUT + co) * CIN + ci] = __float2half(u3);
        }
    }
}

// ---------------------------------------------------------------------------
__global__ void k_style(const float* __restrict__ style,
                        const float* __restrict__ style_w,
                        const float* __restrict__ style_b) {
    __shared__ float sty[SDIM];
    const int n = blockIdx.x;
    const int t = threadIdx.x, lane = t & 31, wp = t >> 5;
    sty[t] = style[n * SDIM + t];
    sty[t + 256] = style[n * SDIM + t + 256];
    __syncthreads();
    const float lin_scale = rsqrtf((float)SDIM);
#pragma unroll
    for (int q = 0; q < 4; q++) {
        int c = blockIdx.y * 32 + wp * 4 + q;
        const float* wr = style_w + (size_t)c * SDIM;
        float acc = 0.f;
#pragma unroll
        for (int i = 0; i < SDIM / 32; i++)
            acc += sty[i * 32 + lane] * wr[i * 32 + lane];
        acc = warp_sum(acc);
        if (lane == 0) g_s[n * CIN + c] = acc * lin_scale + style_b[c];
    }
}

// ---------------------------------------------------------------------------
__global__ void k_demod() {
    __shared__ float s2[CIN];
    const int n = blockIdx.x;
    const int t = threadIdx.x, lane = t & 31, wp = t >> 5;
    float a0 = g_s[n * CIN + t], a1 = g_s[n * CIN + t + 256];
    s2[t] = a0 * a0;
    s2[t + 256] = a1 * a1;
    __syncthreads();
    const float ws = rsqrtf((float)(CIN * 9));
#pragma unroll
    for (int q = 0; q < 4; q++) {
        int o = blockIdx.y * 32 + wp * 4 + q;
        const float* wr = g_wsq + (size_t)o * CIN;
        float acc = 0.f;
#pragma unroll
        for (int i = 0; i < CIN / 32; i++)
            acc += s2[i * 32 + lane] * wr[i * 32 + lane];
        acc = warp_sum(acc);
        if (lane == 0) g_dm[n * COUT + o] = rsqrtf(ws * ws * acc + EPSF);
    }
}

// ---------------------------------------------------------------------------
// V = B^T (x*s) B  fp16 [xi][m][ci], rolling 4-row ring buffer.
// Thread owns 4 consecutive ci x 1 tile column: float4 smem reads, uint2 stores.
// grid = (16 cig, N_ n, 4 strips of 8 ty), block = 256
__global__ void k_vtrans(const float* __restrict__ x) {
    __shared__ float srow[4][66][36];   // ring slot = (y+1)&3; stride 36 -> 16B-aligned float4
    __shared__ float ssc[32];
    const int cig = blockIdx.x, n = blockIdx.y;
    const int ty0 = blockIdx.z * 8;
    const int t = threadIdx.x;

    if (t < 32) ssc[t] = g_s[n * CIN + cig * 32 + t];
    {   // zero halo columns 0 and 65 in all 4 slots (256 threads exactly)
        int r = t >> 6, side = (t >> 5) & 1, ci = t & 31;
        srow[r][side * 65][ci] = 0.f;
    }
    __syncthreads();   // ssc + halo visible before any scaled fill

    const float* xb = x + ((size_t)(n * CIN + cig * 32)) * HH * WW;

    // initial fill: rows y = 2*ty0-1 .. 2*ty0+2
#pragma unroll
    for (int rr = 0; rr < 4; rr++) {
        int y = 2 * ty0 - 1 + rr;
        int slot = (y + 1) & 3;
        int xq = t & 15, ci = t >> 4;
#pragma unroll
        for (int half = 0; half < 2; half++) {
            int cih = ci + half * 16;
            float4 v = make_float4(0.f, 0.f, 0.f, 0.f);
            if (y >= 0 && y < HH)
                v = *(const float4*)&xb[((size_t)cih * HH + y) * WW + xq * 4];
            float sc = ssc[cih];
            srow[slot][xq * 4 + 1][cih] = v.x * sc;
            srow[slot][xq * 4 + 2][cih] = v.y * sc;
            srow[slot][xq * 4 + 3][cih] = v.z * sc;
            srow[slot][xq * 4 + 4][cih] = v.w * sc;
        }
    }
    __syncthreads();

    const int ttx = t >> 3;           // tile column 0..31
    const int tci = (t & 7) * 4;      // ci base within group (0..28 step 4)

    for (int ty = ty0; ty < ty0 + 8; ty++) {
        // ---- transform: 4 ci lanes as float4, one tile column per thread ----
        float4 d[4][4];
#pragma unroll
        for (int r = 0; r < 4; r++) {
            int slot = (2 * ty + r) & 3;
#pragma unroll
            for (int c = 0; c < 4; c++)
                d[r][c] = *(const float4*)&srow[slot][2 * ttx + c][tci];
        }
        float4 z[4][4];
#pragma unroll
        for (int c = 0; c < 4; c++) {
            z[0][c] = f4sub(d[0][c], d[2][c]);
            z[1][c] = f4add(d[1][c], d[2][c]);
            z[2][c] = f4sub(d[2][c], d[1][c]);
            z[3][c] = f4sub(d[1][c], d[3][c]);
        }
        size_t mb = ((size_t)(n * 1024 + ty * 32 + ttx)) * CIN + cig * 32 + tci;
#pragma unroll
        for (int i = 0; i < 4; i++) {
            float4 v[4];
            v[0] = f4sub(z[i][0], z[i][2]);
            v[1] = f4add(z[i][1], z[i][2]);
            v[2] = f4sub(z[i][2], z[i][1]);
            v[3] = f4sub(z[i][1], z[i][3]);
#pragma unroll
            for (int j = 0; j < 4; j++) {
                __half2 h0 = __floats2half2_rn(v[j].x, v[j].y);
                __half2 h1 = __floats2half2_rn(v[j].z, v[j].w);
                uint2 u = make_uint2(*(uint32_t*)&h0, *(uint32_t*)&h1);
                *(uint2*)&g_V[(size_t)(i * 4 + j) * (MTOT * CIN) + mb] = u;
            }
        }
        if (ty + 1 < ty0 + 8) {
            __syncthreads();   // transform reads done before slot overwrite
            // ---- load 2 new rows: y = 2ty+3, 2ty+4 ----
#pragma unroll
            for (int u = 0; u < 4; u++) {
                int id = u * 256 + t;
                int rr = id >> 9;
                int rem = id & 511;
                int xq = rem & 15, ci = rem >> 4;
                int y = 2 * ty + 3 + rr;
                int slot = (y + 1) & 3;
                float4 v = make_float4(0.f, 0.f, 0.f, 0.f);
                if (y < HH)
                    v = *(const float4*)&xb[((size_t)ci * HH + y) * WW + xq * 4];
                float sc = ssc[ci];
                srow[slot][xq * 4 + 1][ci] = v.x * sc;
                srow[slot][xq * 4 + 2][ci] = v.y * sc;
                srow[slot][xq * 4 + 3][ci] = v.z * sc;
                srow[slot][xq * 4 + 4][ci] = v.w * sc;
            }
            __syncthreads();
        }
    }
}

// ---------------------------------------------------------------------------
// Stage loader: A = V[xi][m0..+128][32ci], B = U[xi][co0..+128][32ci]
__device__ __forceinline__ void load_stage(uint32_t sbase, int xi, int m0, int co0,
                                           int cic, int t) {
#pragma unroll
    for (int u = 0; u < 2; u++) {
        int id = u * 256 + t;
        int row = id >> 2, seg = id & 3;
        const __half* src = g_V + ((size_t)xi * MTOT + m0 + row) * CIN + cic * KCH + seg * 8;
        cp16(sbase + row * ROWB + seg * 16, src);
    }
#pragma unroll
    for (int u = 0; u < 2; u++) {
        int id = u * 256 + t;
        int row = id >> 2, seg = id & 3;
        const __half* src = g_U + ((size_t)xi * COUT + co0 + row) * CIN + cic * KCH + seg * 8;
        cp16(sbase + ARR_B + row * ROWB + seg * 16, src);
    }
}

// ---------------------------------------------------------------------------
// Winograd-domain GEMM: M[xi][co][m] = V[xi][m][ci] * U[xi][co][ci], fp16 out.
__global__ void __launch_bounds__(256, 2)
k_gemm() {
    extern __shared__ __align__(16) char smem[];
    const uint32_t sb = smem_u32(smem);

    const int t = threadIdx.x;
    const int lane = t & 31;
    const int w = t >> 5;
    const int warp_m = w & 3;
    const int warp_n = w >> 2;
    const int m0 = blockIdx.x * TILE_M;
    const int co0 = blockIdx.y * TILE_N;
    const int xi = blockIdx.z;

    const uint32_t a_off =
        (uint32_t)((warp_m * 32 + (lane & 15)) * ROWB + (lane >> 4) * 16);
    const uint32_t b_off =
        (uint32_t)(ARR_B +
                   (warp_n * 64 + (lane & 7) + (lane >> 4) * 8) * ROWB +
                   ((lane >> 3) & 1) * 16);

    float acc[2][8][4];
#pragma unroll
    for (int mt = 0; mt < 2; mt++)
#pragma unroll
        for (int nt = 0; nt < 8; nt++)
#pragma unroll
            for (int q = 0; q < 4; q++) acc[mt][nt][q] = 0.f;

    load_stage(sb + 0 * STAGE_B, xi, m0, co0, 0, t);
    CP_COMMIT();
    load_stage(sb + 1 * STAGE_B, xi, m0, co0, 1, t);
    CP_COMMIT();

    int st = 0;
    for (int j = 0; j < NITER; j++) {
        if (j + 2 < NITER) {
            int s2 = (j + 2) % STAGES;
            load_stage(sb + s2 * STAGE_B, xi, m0, co0, j + 2, t);
        }
        CP_COMMIT();
        CP_WAIT2();
        __syncthreads();

        const uint32_t base = sb + st * STAGE_B;
#pragma unroll
        for (int ks = 0; ks < 2; ks++) {
            const uint32_t ko = ks * 32;
            uint32_t ah[2][4];
#pragma unroll
            for (int mt = 0; mt < 2; mt++)
                ldm_x4(ah[mt], base + a_off + mt * 16 * ROWB + ko);
            uint32_t bh[4][4];
#pragma unroll
            for (int p = 0; p < 4; p++)
                ldm_x4(bh[p], base + b_off + p * 16 * ROWB + ko);
#pragma unroll
            for (int mt = 0; mt < 2; mt++) {
#pragma unroll
                for (int nt = 0; nt < 8; nt++) {
                    const int p = nt >> 1, h = (nt & 1) * 2;
                    mma_f16(acc[mt][nt], ah[mt], bh[p][h], bh[p][h + 1]);
                }
            }
        }
        __syncthreads();
        st = (st + 1) % STAGES;
    }

    // epilogue: fp16 store
#pragma unroll
    for (int mt = 0; mt < 2; mt++) {
#pragma unroll
        for (int nt = 0; nt < 8; nt++) {
            int r = warp_m * 32 + mt * 16 + (lane >> 2);
            int c = warp_n * 64 + nt * 8 + (lane & 3) * 2;
            size_t b0 = ((size_t)xi * COUT + co0 + c) * MTOT + m0;
            g_M[b0 + r] = __float2half(acc[mt][nt][0]);
            g_M[b0 + MTOT + r] = __float2half(acc[mt][nt][1]);
            g_M[b0 + r + 8] = __float2half(acc[mt][nt][2]);
            g_M[b0 + MTOT + r + 8] = __float2half(acc[mt][nt][3]);
        }
    }
}

// ---------------------------------------------------------------------------
// Y = A^T M A, * demod, scatter to NCHW.  grid = (COUT, N_), block = 256.
__global__ void k_ytrans(float* __restrict__ out) {
    extern __shared__ __align__(16) __half sm[];   // [16][1024]
    const int co = blockIdx.x, n = blockIdx.y;
    const int t = threadIdx.x;

#pragma unroll
    for (int u = 0; u < 8; u++) {
        int id = u * 256 + t;
        int xi = id >> 7, h8 = id & 127;
        ((uint4*)sm)[id] = *(const uint4*)
            &g_M[((size_t)xi * COUT + co) * MTOT + (size_t)n * 1024 + h8 * 8];
    }
    __syncthreads();

    const float dm = g_dm[n * COUT + co];
#pragma unroll
    for (int p = 0; p < 4; p++) {
        int tile = p * 256 + t;
        int ty = tile >> 5, tx = tile & 31;
        float m[4][4];
#pragma unroll
        for (int xi = 0; xi < 16; xi++)
            m[xi >> 2][xi & 3] = __half2float(sm[xi * 1024 + tile]);
        float z[2][4];
#pragma unroll
        for (int c = 0; c < 4; c++) {
            z[0][c] = m[0][c] + m[1][c] + m[2][c];
            z[1][c] = m[1][c] - m[2][c] - m[3][c];
        }
        size_t ob = (((size_t)(n * COUT + co)) * HH + 2 * ty) * WW + 2 * tx;
        float2 r0 = make_float2((z[0][0] + z[0][1] + z[0][2]) * dm,
                                (z[0][1] - z[0][2] - z[0][3]) * dm);
        float2 r1 = make_float2((z[1][0] + z[1][1] + z[1][2]) * dm,
                                (z[1][1] - z[1][2] - z[1][3]) * dm);
        *(float2*)&out[ob] = r0;
        *(float2*)&out[ob + WW] = r1;
    }
}

// ---------------------------------------------------------------------------
extern "C" void kernel_launch(void* const* d_in, const int* in_sizes, int n_in,
                              void* d_out, int out_size) {
    const float* x       = (const float*)d_in[0];   // [16,512,64,64]
    const float* style   = (const float*)d_in[1];   // [16,512]
    const float* weight  = (const float*)d_in[2];   // [512,512,3,3]
    const float* style_w = (const float*)d_in[3];   // [512,512]
    const float* style_b = (const float*)d_in[4];   // [512]
    float* out = (float*)d_out;                     // [16,512,64,64]

    k_wprep<<<COUT, 256>>>(weight);
    dim3 sg(N_, 16);
    k_style<<<sg, 256>>>(style, style_w, style_b);
    k_demod<<<sg, 256>>>();
    dim3 vg(16, N_, 4);
    k_vtrans<<<vg, 256>>>(x);

    cudaFuncSetAttribute(k_gemm, cudaFuncAttributeMaxDynamicSharedMemorySize, SMEM_TOTAL);
    dim3 gg(MTOT / TILE_M, COUT / TILE_N, 16);      // (128, 4, 16)
    k_gemm<<<gg, 256, SMEM_TOTAL>>>();

    cudaFuncSetAttribute(k_ytrans, cudaFuncAttributeMaxDynamicSharedMemorySize, 32768);
    dim3 yg(COUT, N_);
    k_ytrans<<<yg, 256, 32768>>>(out);
}